// round 3
// baseline (speedup 1.0000x reference)
#include <cuda_runtime.h>

#define NN   50000
#define NE   800000
#define FIN  128
#define NH1  8
#define HID  32
#define F1   256   // NH1*HID
#define NOUT 40
#define CAP  512   // smem edge cap per dst (max degree ~50 for Poisson(16); fallback is exact)

// ---------------- scratch (device globals; no allocation allowed) ----------------
__device__ float g_z1[(size_t)NN * F1];     // feat @ W1
__device__ float g_h1[(size_t)NN * F1];     // elu(agg1 + b1)
__device__ float g_z2[(size_t)NN * NOUT];   // h1 @ W2
__device__ float g_el1[NN * NH1];
__device__ float g_er1[NN * NH1];
__device__ float g_el2[NN];
__device__ float g_er2[NN];
__device__ int   g_deg[NN];                 // zeroed by agg1 each call (invariant)
__device__ int   g_cursor[NN];              // zeroed by scan each call
__device__ int   g_rowptr[NN + 1];
__device__ int   g_srcs[NE];                // src node per CSR slot

// ---------------- CSR build ----------------
__global__ void count_kernel(const int* __restrict__ dst) {
    int e = blockIdx.x * blockDim.x + threadIdx.x;
    if (e < NE) atomicAdd(&g_deg[dst[e]], 1);
}

__global__ void scan_kernel() {
    __shared__ int sums[1024];
    int tid = threadIdx.x;
    const int chunk = (NN + 1023) / 1024;
    int start = tid * chunk;
    int end = start + chunk; if (end > NN) end = NN;
    int local = 0;
    for (int i = start; i < end; i++) local += g_deg[i];
    sums[tid] = local;
    __syncthreads();
    for (int off = 1; off < 1024; off <<= 1) {
        int v = 0;
        if (tid >= off) v = sums[tid - off];
        __syncthreads();
        if (tid >= off) sums[tid] += v;
        __syncthreads();
    }
    int run = (tid == 0) ? 0 : sums[tid - 1];
    for (int i = start; i < end; i++) {
        g_rowptr[i] = run;
        run += g_deg[i];
        g_cursor[i] = 0;   // reset for scatter
    }
    if (tid == 1023) g_rowptr[NN] = run;
}

__global__ void scatter_kernel(const int* __restrict__ src, const int* __restrict__ dst) {
    int e = blockIdx.x * blockDim.x + threadIdx.x;
    if (e >= NE) return;
    int d = dst[e];
    int p = atomicAdd(&g_cursor[d], 1);
    g_srcs[g_rowptr[d] + p] = src[e];
}

// ---------------- GEMM1: z1[NN,256] = feat[NN,128] @ W1[128,256], fused el1/er1 ----------------
__global__ __launch_bounds__(256) void gemm1_kernel(const float* __restrict__ A,
                                                    const float* __restrict__ B,
                                                    const float* __restrict__ al,
                                                    const float* __restrict__ ar) {
    const int K = FIN, N = F1, BK = 16;
    __shared__ float As[2][BK][128];
    __shared__ float Bs[2][BK][128];
    int tid = threadIdx.x;
    int brow = blockIdx.y * 128, bcol = blockIdx.x * 128;
    int tx = tid & 15, ty = tid >> 4;

    int arow = tid & 127;
    int ak = (tid >> 7) * 8;
    int brw = tid >> 4;
    int bcl = (tid & 15) * 8;

    int gr = brow + arow;
    bool rok = gr < NN;
    const float* Ap = A + (size_t)(rok ? gr : 0) * K;

    float acc[8][8];
#pragma unroll
    for (int i = 0; i < 8; i++)
#pragma unroll
        for (int j = 0; j < 8; j++) acc[i][j] = 0.f;

    float4 pa0, pa1, pb0, pb1;
    const float4 z4 = make_float4(0.f, 0.f, 0.f, 0.f);

    pa0 = rok ? *reinterpret_cast<const float4*>(Ap + ak) : z4;
    pa1 = rok ? *reinterpret_cast<const float4*>(Ap + ak + 4) : z4;
    pb0 = *reinterpret_cast<const float4*>(B + (size_t)brw * N + bcol + bcl);
    pb1 = *reinterpret_cast<const float4*>(B + (size_t)brw * N + bcol + bcl + 4);
    {
        As[0][ak + 0][arow] = pa0.x; As[0][ak + 1][arow] = pa0.y;
        As[0][ak + 2][arow] = pa0.z; As[0][ak + 3][arow] = pa0.w;
        As[0][ak + 4][arow] = pa1.x; As[0][ak + 5][arow] = pa1.y;
        As[0][ak + 6][arow] = pa1.z; As[0][ak + 7][arow] = pa1.w;
        *reinterpret_cast<float4*>(&Bs[0][brw][bcl]) = pb0;
        *reinterpret_cast<float4*>(&Bs[0][brw][bcl + 4]) = pb1;
    }
    __syncthreads();

    int buf = 0;
    for (int k0 = 0; k0 < K; k0 += BK) {
        bool more = (k0 + BK) < K;
        if (more) {
            int kn = k0 + BK;
            pa0 = rok ? *reinterpret_cast<const float4*>(Ap + kn + ak) : z4;
            pa1 = rok ? *reinterpret_cast<const float4*>(Ap + kn + ak + 4) : z4;
            pb0 = *reinterpret_cast<const float4*>(B + (size_t)(kn + brw) * N + bcol + bcl);
            pb1 = *reinterpret_cast<const float4*>(B + (size_t)(kn + brw) * N + bcol + bcl + 4);
        }
#pragma unroll
        for (int kk = 0; kk < BK; kk++) {
            float ar8[8], br8[8];
            *reinterpret_cast<float4*>(&ar8[0]) = *reinterpret_cast<const float4*>(&As[buf][kk][ty * 8]);
            *reinterpret_cast<float4*>(&ar8[4]) = *reinterpret_cast<const float4*>(&As[buf][kk][ty * 8 + 4]);
            *reinterpret_cast<float4*>(&br8[0]) = *reinterpret_cast<const float4*>(&Bs[buf][kk][tx * 8]);
            *reinterpret_cast<float4*>(&br8[4]) = *reinterpret_cast<const float4*>(&Bs[buf][kk][tx * 8 + 4]);
#pragma unroll
            for (int i = 0; i < 8; i++)
#pragma unroll
                for (int j = 0; j < 8; j++) acc[i][j] += ar8[i] * br8[j];
        }
        if (more) {
            int nb = buf ^ 1;
            As[nb][ak + 0][arow] = pa0.x; As[nb][ak + 1][arow] = pa0.y;
            As[nb][ak + 2][arow] = pa0.z; As[nb][ak + 3][arow] = pa0.w;
            As[nb][ak + 4][arow] = pa1.x; As[nb][ak + 5][arow] = pa1.y;
            As[nb][ak + 6][arow] = pa1.z; As[nb][ak + 7][arow] = pa1.w;
            *reinterpret_cast<float4*>(&Bs[nb][brw][bcl]) = pb0;
            *reinterpret_cast<float4*>(&Bs[nb][brw][bcl + 4]) = pb1;
            __syncthreads();
            buf = nb;
        }
    }

    int head = (bcol >> 5) + (tx >> 2);
    int cw = (tx & 3) * 8;
    float alv[8], arv[8];
#pragma unroll
    for (int j = 0; j < 8; j++) {
        alv[j] = al[head * HID + cw + j];
        arv[j] = ar[head * HID + cw + j];
    }
#pragma unroll
    for (int i = 0; i < 8; i++) {
        int r = brow + ty * 8 + i;
        float pl = 0.f, pr = 0.f;
#pragma unroll
        for (int j = 0; j < 8; j++) { pl += acc[i][j] * alv[j]; pr += acc[i][j] * arv[j]; }
        pl += __shfl_xor_sync(0xffffffffu, pl, 1);
        pl += __shfl_xor_sync(0xffffffffu, pl, 2);
        pr += __shfl_xor_sync(0xffffffffu, pr, 1);
        pr += __shfl_xor_sync(0xffffffffu, pr, 2);
        if (r < NN) {
            float* cp = g_z1 + (size_t)r * N + bcol + tx * 8;
            *reinterpret_cast<float4*>(cp) = *reinterpret_cast<float4*>(&acc[i][0]);
            *reinterpret_cast<float4*>(cp + 4) = *reinterpret_cast<float4*>(&acc[i][4]);
            if ((tx & 3) == 0) {
                g_el1[r * NH1 + head] = pl;
                g_er1[r * NH1 + head] = pr;
            }
        }
    }
}

// ---------------- fused softmax+aggregation layer 1: block(256) per dst ----------------
__global__ __launch_bounds__(256) void agg1_kernel(const float* __restrict__ b1) {
    __shared__ int ssrc[CAP];
    __shared__ float ev[NH1][CAP];
    int dst = blockIdx.x;
    int tid = threadIdx.x;
    int lane = tid & 31;
    int h = tid >> 5;
    int s = g_rowptr[dst], e = g_rowptr[dst + 1];
    int deg = e - s;
    if (tid == 0) g_deg[dst] = 0;   // restore invariant for next call's count_kernel
    int dcap = deg < CAP ? deg : CAP;
    for (int i = tid; i < dcap; i += 256) ssrc[i] = g_srcs[s + i];
    __syncthreads();

    float erh = g_er1[dst * NH1 + h];

    // pass 1: logits + max (warp h handles head h)
    float mx = -1e30f;
    for (int i = lane; i < deg; i += 32) {
        int src = (i < CAP) ? ssrc[i] : g_srcs[s + i];
        float v = g_el1[src * NH1 + h] + erh;
        v = v > 0.f ? v : 0.2f * v;
        if (i < CAP) ev[h][i] = v;
        mx = fmaxf(mx, v);
    }
#pragma unroll
    for (int o = 16; o > 0; o >>= 1) mx = fmaxf(mx, __shfl_xor_sync(0xffffffffu, mx, o));

    // pass 2: exp + sum
    float sm = 0.f;
    for (int i = lane; i < deg; i += 32) {
        float v;
        if (i < CAP) v = ev[h][i];
        else {
            int src = g_srcs[s + i];
            v = g_el1[src * NH1 + h] + erh;
            v = v > 0.f ? v : 0.2f * v;
        }
        float x = __expf(v - mx);
        if (i < CAP) ev[h][i] = x;
        sm += x;
    }
#pragma unroll
    for (int o = 16; o > 0; o >>= 1) sm += __shfl_xor_sync(0xffffffffu, sm, o);
    float rden = sm > 0.f ? 1.f / sm : 0.f;
    __syncthreads();

    // pass 3: weighted aggregation (thread tid = feature column; its warp == its head)
    float acc = 0.f;
    int i = 0;
    int dn = dcap & ~3;
    for (; i < dn; i += 4) {
        int s0 = ssrc[i], s1 = ssrc[i + 1], s2 = ssrc[i + 2], s3 = ssrc[i + 3];
        float w0 = ev[h][i], w1 = ev[h][i + 1], w2 = ev[h][i + 2], w3 = ev[h][i + 3];
        float v0 = g_z1[(size_t)s0 * F1 + tid];
        float v1 = g_z1[(size_t)s1 * F1 + tid];
        float v2 = g_z1[(size_t)s2 * F1 + tid];
        float v3 = g_z1[(size_t)s3 * F1 + tid];
        acc = fmaf(w0, v0, acc); acc = fmaf(w1, v1, acc);
        acc = fmaf(w2, v2, acc); acc = fmaf(w3, v3, acc);
    }
    for (; i < deg; i++) {
        int src; float w;
        if (i < CAP) { src = ssrc[i]; w = ev[h][i]; }
        else {
            src = g_srcs[s + i];
            float v = g_el1[src * NH1 + h] + erh;
            v = v > 0.f ? v : 0.2f * v;
            w = __expf(v - mx);
        }
        acc = fmaf(w, g_z1[(size_t)src * F1 + tid], acc);
    }
    float o = acc * rden + b1[tid];
    g_h1[(size_t)dst * F1 + tid] = o > 0.f ? o : (__expf(o) - 1.f);
}

// ---------------- GEMM2: z2[NN,40] = h1[NN,256] @ W2[256,40], fused el2/er2 ----------------
__global__ __launch_bounds__(256) void gemm2_kernel(const float* __restrict__ W,
                                                    const float* __restrict__ al2,
                                                    const float* __restrict__ ar2) {
    __shared__ float Ws[F1][NOUT];  // 40 KB
    int tid = threadIdx.x;
    for (int i = tid; i < F1 * NOUT; i += 256) Ws[i / NOUT][i % NOUT] = W[i];
    __syncthreads();

    int r0 = blockIdx.x * 256 + (tid >> 2) * 4;
    int c0 = (tid & 3) * 10;
    float acc[4][10];
#pragma unroll
    for (int i = 0; i < 4; i++)
#pragma unroll
        for (int j = 0; j < 10; j++) acc[i][j] = 0.f;

    bool valid[4];
    const float* ap[4];
#pragma unroll
    for (int i = 0; i < 4; i++) {
        valid[i] = (r0 + i) < NN;
        ap[i] = g_h1 + (size_t)(valid[i] ? (r0 + i) : 0) * F1;
    }
    for (int k0 = 0; k0 < F1; k0 += 4) {
        float4 av[4];
#pragma unroll
        for (int i = 0; i < 4; i++)
            av[i] = valid[i] ? *reinterpret_cast<const float4*>(ap[i] + k0)
                             : make_float4(0.f, 0.f, 0.f, 0.f);
#pragma unroll
        for (int kk = 0; kk < 4; kk++) {
            float a[4];
#pragma unroll
            for (int i = 0; i < 4; i++) a[i] = reinterpret_cast<const float*>(&av[i])[kk];
#pragma unroll
            for (int j = 0; j < 10; j++) {
                float wv = Ws[k0 + kk][c0 + j];
#pragma unroll
                for (int i = 0; i < 4; i++) acc[i][j] += a[i] * wv;
            }
        }
    }

    float alv[10], arv[10];
#pragma unroll
    for (int j = 0; j < 10; j++) { alv[j] = al2[c0 + j]; arv[j] = ar2[c0 + j]; }
#pragma unroll
    for (int i = 0; i < 4; i++) {
        float pl = 0.f, pr = 0.f;
#pragma unroll
        for (int j = 0; j < 10; j++) { pl += acc[i][j] * alv[j]; pr += acc[i][j] * arv[j]; }
        pl += __shfl_xor_sync(0xffffffffu, pl, 1);
        pl += __shfl_xor_sync(0xffffffffu, pl, 2);
        pr += __shfl_xor_sync(0xffffffffu, pr, 1);
        pr += __shfl_xor_sync(0xffffffffu, pr, 2);
        int r = r0 + i;
        if (r < NN) {
            float* cp = g_z2 + (size_t)r * NOUT + c0;
#pragma unroll
            for (int j = 0; j < 10; j++) cp[j] = acc[i][j];
            if ((tid & 3) == 0) { g_el2[r] = pl; g_er2[r] = pr; }
        }
    }
}

// ---------------- fused softmax+aggregation layer 2 -> output ----------------
__global__ __launch_bounds__(64) void agg2_kernel(const float* __restrict__ b2,
                                                  float* __restrict__ out) {
    __shared__ int ssrc[CAP];
    __shared__ float ev[CAP];
    __shared__ float sh_mx, sh_rden;
    int dst = blockIdx.x;
    int tid = threadIdx.x;
    int lane = tid & 31;
    int s = g_rowptr[dst], e = g_rowptr[dst + 1];
    int deg = e - s;
    int dcap = deg < CAP ? deg : CAP;
    for (int i = tid; i < dcap; i += 64) ssrc[i] = g_srcs[s + i];
    __syncthreads();

    float erh = g_er2[dst];
    if (tid < 32) {
        float mx = -1e30f;
        for (int i = lane; i < deg; i += 32) {
            int src = (i < CAP) ? ssrc[i] : g_srcs[s + i];
            float v = g_el2[src] + erh;
            v = v > 0.f ? v : 0.2f * v;
            if (i < CAP) ev[i] = v;
            mx = fmaxf(mx, v);
        }
#pragma unroll
        for (int o = 16; o > 0; o >>= 1) mx = fmaxf(mx, __shfl_xor_sync(0xffffffffu, mx, o));
        float sm = 0.f;
        for (int i = lane; i < deg; i += 32) {
            float v;
            if (i < CAP) v = ev[i];
            else {
                int src = g_srcs[s + i];
                v = g_el2[src] + erh;
                v = v > 0.f ? v : 0.2f * v;
            }
            float x = __expf(v - mx);
            if (i < CAP) ev[i] = x;
            sm += x;
        }
#pragma unroll
        for (int o = 16; o > 0; o >>= 1) sm += __shfl_xor_sync(0xffffffffu, sm, o);
        if (lane == 0) {
            sh_mx = mx;
            sh_rden = sm > 0.f ? 1.f / sm : 0.f;
        }
    }
    __syncthreads();
    float mx = sh_mx, rden = sh_rden;

    if (tid < NOUT) {
        float acc = 0.f;
        int i = 0;
        int dn = dcap & ~3;
        for (; i < dn; i += 4) {
            int s0 = ssrc[i], s1 = ssrc[i + 1], s2 = ssrc[i + 2], s3 = ssrc[i + 3];
            float w0 = ev[i], w1 = ev[i + 1], w2 = ev[i + 2], w3 = ev[i + 3];
            float v0 = g_z2[(size_t)s0 * NOUT + tid];
            float v1 = g_z2[(size_t)s1 * NOUT + tid];
            float v2 = g_z2[(size_t)s2 * NOUT + tid];
            float v3 = g_z2[(size_t)s3 * NOUT + tid];
            acc = fmaf(w0, v0, acc); acc = fmaf(w1, v1, acc);
            acc = fmaf(w2, v2, acc); acc = fmaf(w3, v3, acc);
        }
        for (; i < deg; i++) {
            int src; float w;
            if (i < CAP) { src = ssrc[i]; w = ev[i]; }
            else {
                src = g_srcs[s + i];
                float v = g_el2[src] + erh;
                v = v > 0.f ? v : 0.2f * v;
                w = __expf(v - mx);
            }
            acc = fmaf(w, g_z2[(size_t)src * NOUT + tid], acc);
        }
        out[dst * NOUT + tid] = acc * rden + b2[tid];
    }
}

// ---------------- launch ----------------
extern "C" void kernel_launch(void* const* d_in, const int* in_sizes, int n_in,
                              void* d_out, int out_size) {
    const float* feat = (const float*)d_in[0];
    const int* src = (const int*)d_in[1];
    const int* dst = (const int*)d_in[2];
    const float* W1 = (const float*)d_in[3];
    const float* al1 = (const float*)d_in[4];
    const float* ar1 = (const float*)d_in[5];
    const float* b1 = (const float*)d_in[6];
    const float* W2 = (const float*)d_in[7];
    const float* al2 = (const float*)d_in[8];
    const float* ar2 = (const float*)d_in[9];
    const float* b2 = (const float*)d_in[10];
    float* out = (float*)d_out;

    // CSR by destination (g_deg zeroed by previous call's agg1 / static init)
    count_kernel<<<(NE + 255) / 256, 256>>>(dst);
    scan_kernel<<<1, 1024>>>();
    scatter_kernel<<<(NE + 255) / 256, 256>>>(src, dst);

    // layer 1
    gemm1_kernel<<<dim3(2, (NN + 127) / 128), 256>>>(feat, W1, al1, ar1);
    agg1_kernel<<<NN, 256>>>(b1);

    // layer 2
    gemm2_kernel<<<(NN + 255) / 256, 256>>>(W2, al2, ar2);
    agg2_kernel<<<NN, 64>>>(b2, out);
}

// round 5
// speedup vs baseline: 1.0298x; 1.0298x over previous
#include <cuda_runtime.h>
#include <cstdint>

#define NN   50000
#define NE   800000
#define FIN  128
#define NH1  8
#define HID  32
#define F1   256   // NH1*HID
#define NOUT 40
#define CAP  512   // smem edge cap per dst (max degree ~50 for Poisson(16); fallback is exact)

// GEMM1 tiling
#define G1_BM 128
#define G1_BK 32
#define AS_STRIDE 36    // 32 + 4 pad (floats); 144B = 9*16 (cp.async aligned), +4 banks/row
#define BS_STRIDE 260   // 256 + 4 pad; 1040B = 65*16, +4 banks/row
#define AS_ELEMS (G1_BM * AS_STRIDE)          // 4608
#define BS_ELEMS (G1_BK * BS_STRIDE)          // 8320
#define G1_SMEM_BYTES ((2 * AS_ELEMS + 2 * BS_ELEMS) * 4)   // 103424

// ---------------- scratch (device globals; no allocation allowed) ----------------
__device__ float g_z1[(size_t)NN * F1];     // feat @ W1
__device__ float g_h1[(size_t)NN * F1];     // elu(agg1 + b1)
__device__ float g_z2[(size_t)NN * NOUT];   // h1 @ W2
__device__ float g_el1[NN * NH1];
__device__ float g_er1[NN * NH1];
__device__ float g_el2[NN];
__device__ float g_er2[NN];
__device__ int   g_deg[NN];                 // zeroed by agg1 each call (invariant)
__device__ int   g_cursor[NN];              // zeroed by scan each call
__device__ int   g_rowptr[NN + 1];
__device__ int   g_srcs[NE];                // src node per CSR slot

// ---------------- CSR build ----------------
__global__ void count_kernel(const int* __restrict__ dst) {
    int e = blockIdx.x * blockDim.x + threadIdx.x;
    if (e < NE) atomicAdd(&g_deg[dst[e]], 1);
}

__global__ void scan_kernel() {
    __shared__ int sums[1024];
    int tid = threadIdx.x;
    const int chunk = (NN + 1023) / 1024;
    int start = tid * chunk;
    int end = start + chunk; if (end > NN) end = NN;
    int local = 0;
    for (int i = start; i < end; i++) local += g_deg[i];
    sums[tid] = local;
    __syncthreads();
    for (int off = 1; off < 1024; off <<= 1) {
        int v = 0;
        if (tid >= off) v = sums[tid - off];
        __syncthreads();
        if (tid >= off) sums[tid] += v;
        __syncthreads();
    }
    int run = (tid == 0) ? 0 : sums[tid - 1];
    for (int i = start; i < end; i++) {
        g_rowptr[i] = run;
        run += g_deg[i];
        g_cursor[i] = 0;   // reset for scatter
    }
    if (tid == 1023) g_rowptr[NN] = run;
}

__global__ void scatter_kernel(const int* __restrict__ src, const int* __restrict__ dst) {
    int e = blockIdx.x * blockDim.x + threadIdx.x;
    if (e >= NE) return;
    int d = dst[e];
    int p = atomicAdd(&g_cursor[d], 1);
    g_srcs[g_rowptr[d] + p] = src[e];
}

// ---------------- tf32 helpers ----------------
__device__ __forceinline__ uint32_t f2tf32(float x) {
    uint32_t r;
    asm("cvt.rna.tf32.f32 %0, %1;" : "=r"(r) : "f"(x));
    return r;
}
__device__ __forceinline__ void tf32_split(float x, uint32_t& hi, uint32_t& lo) {
    hi = f2tf32(x);
    lo = f2tf32(x - __uint_as_float(hi));
}
__device__ __forceinline__ void mma_tf32(float* d, const uint32_t* a, uint32_t b0, uint32_t b1) {
    asm volatile(
        "mma.sync.aligned.m16n8k8.row.col.f32.tf32.tf32.f32 "
        "{%0,%1,%2,%3},{%4,%5,%6,%7},{%8,%9},{%0,%1,%2,%3};"
        : "+f"(d[0]), "+f"(d[1]), "+f"(d[2]), "+f"(d[3])
        : "r"(a[0]), "r"(a[1]), "r"(a[2]), "r"(a[3]), "r"(b0), "r"(b1));
}
__device__ __forceinline__ void cpa16(uint32_t dst, const void* src, bool ok) {
    asm volatile("cp.async.cg.shared.global [%0], [%1], 16, %2;"
                 :: "r"(dst), "l"(src), "r"(ok ? 16 : 0));
}
__device__ __forceinline__ void cpa_commit() { asm volatile("cp.async.commit_group;"); }
template <int N>
__device__ __forceinline__ void cpa_wait() { asm volatile("cp.async.wait_group %0;" :: "n"(N)); }

// ---------------- GEMM1 (tensor core, tf32 3-term): z1 = feat @ W1, fused el1/er1 ----------------
__global__ __launch_bounds__(256) void gemm1_kernel(const float* __restrict__ A,
                                                    const float* __restrict__ B,
                                                    const float* __restrict__ al,
                                                    const float* __restrict__ ar) {
    extern __shared__ float sm[];
    float* Asm[2] = { sm, sm + AS_ELEMS };
    float* Bsm[2] = { sm + 2 * AS_ELEMS, sm + 2 * AS_ELEMS + BS_ELEMS };

    int tid = threadIdx.x;
    int wid = tid >> 5, lane = tid & 31;
    int wm = wid >> 2;          // 0..1  (64 rows each)
    int wn = wid & 3;           // 0..3  (64 cols each)
    int r = lane >> 2, c = lane & 3;
    int brow = blockIdx.x * G1_BM;

    // ---- cp.async issue ----
    int la_row = tid >> 1;                 // 0..127
    int la_kq = (tid & 1) * 16;            // 0 or 16
    int la_gr = brow + la_row;
    bool la_ok = la_gr < NN;
    const float* la_src = A + (size_t)(la_ok ? la_gr : 0) * FIN + la_kq;
    int lb_row = tid >> 3;                 // 0..31
    int lb_col = (tid & 7) * 32;           // 0..224

    auto issue = [&](int kc, int buf) {
        uint32_t ad = (uint32_t)__cvta_generic_to_shared(Asm[buf] + la_row * AS_STRIDE + la_kq);
        const float* as = la_src + kc * G1_BK;
#pragma unroll
        for (int i = 0; i < 4; i++) cpa16(ad + i * 16, as + i * 4, la_ok);
        uint32_t bd = (uint32_t)__cvta_generic_to_shared(Bsm[buf] + lb_row * BS_STRIDE + lb_col);
        const float* bs = B + (size_t)(kc * G1_BK + lb_row) * F1 + lb_col;
#pragma unroll
        for (int i = 0; i < 8; i++) cpa16(bd + i * 16, bs + i * 4, true);
    };

    float acc[4][8][4];
#pragma unroll
    for (int mt = 0; mt < 4; mt++)
#pragma unroll
        for (int nt = 0; nt < 8; nt++)
#pragma unroll
            for (int j = 0; j < 4; j++) acc[mt][nt][j] = 0.f;

    issue(0, 0); cpa_commit();
    issue(1, 1); cpa_commit();
    cpa_wait<1>();
    __syncthreads();

#pragma unroll
    for (int kc = 0; kc < 4; kc++) {
        int buf = kc & 1;
        const float* as = Asm[buf];
        const float* bs = Bsm[buf];
#pragma unroll
        for (int ks = 0; ks < 4; ks++) {
            int k0 = ks * 8;
            uint32_t bh0[8], bl0[8], bh1[8], bl1[8];
            int bcol = wn * 64 + r;
#pragma unroll
            for (int nt = 0; nt < 8; nt++) {
                float b0 = bs[(k0 + c) * BS_STRIDE + bcol + nt * 8];
                float b1 = bs[(k0 + 4 + c) * BS_STRIDE + bcol + nt * 8];
                tf32_split(b0, bh0[nt], bl0[nt]);
                tf32_split(b1, bh1[nt], bl1[nt]);
            }
#pragma unroll
            for (int mt = 0; mt < 4; mt++) {
                int mr = wm * 64 + mt * 16 + r;
                float a0 = as[mr * AS_STRIDE + k0 + c];
                float a1 = as[(mr + 8) * AS_STRIDE + k0 + c];
                float a2 = as[mr * AS_STRIDE + k0 + 4 + c];
                float a3 = as[(mr + 8) * AS_STRIDE + k0 + 4 + c];
                uint32_t ah[4], alo[4];
                tf32_split(a0, ah[0], alo[0]);
                tf32_split(a1, ah[1], alo[1]);
                tf32_split(a2, ah[2], alo[2]);
                tf32_split(a3, ah[3], alo[3]);
#pragma unroll
                for (int nt = 0; nt < 8; nt++) {
                    mma_tf32(acc[mt][nt], ah, bh0[nt], bh1[nt]);
                    mma_tf32(acc[mt][nt], alo, bh0[nt], bh1[nt]);
                    mma_tf32(acc[mt][nt], ah, bl0[nt], bl1[nt]);
                }
            }
        }
        __syncthreads();
        if (kc == 0 || kc == 1) issue(kc + 2, buf);
        cpa_commit();
        if (kc < 3) {
            cpa_wait<1>();
            __syncthreads();
        }
    }

    // ---- epilogue: z1 store + fused el1/er1 ----
    float alv[16], arv[16];
#pragma unroll
    for (int nt = 0; nt < 8; nt++)
#pragma unroll
        for (int j = 0; j < 2; j++) {
            int head = wn * 2 + (nt >> 2);
            int cih = (nt & 3) * 8 + c * 2 + j;
            alv[nt * 2 + j] = al[head * HID + cih];
            arv[nt * 2 + j] = ar[head * HID + cih];
        }

#pragma unroll
    for (int mt = 0; mt < 4; mt++) {
        int r0 = brow + wm * 64 + mt * 16 + r;
        int r1 = r0 + 8;
        float el[2][2] = {{0.f, 0.f}, {0.f, 0.f}};
        float er_[2][2] = {{0.f, 0.f}, {0.f, 0.f}};
#pragma unroll
        for (int nt = 0; nt < 8; nt++) {
            int hh = nt >> 2;
#pragma unroll
            for (int j = 0; j < 2; j++) {
                float av = alv[nt * 2 + j], rv = arv[nt * 2 + j];
                el[hh][0] += acc[mt][nt][j] * av;
                er_[hh][0] += acc[mt][nt][j] * rv;
                el[hh][1] += acc[mt][nt][2 + j] * av;
                er_[hh][1] += acc[mt][nt][2 + j] * rv;
            }
        }
#pragma unroll
        for (int hh = 0; hh < 2; hh++)
#pragma unroll
            for (int hf = 0; hf < 2; hf++) {
                el[hh][hf] += __shfl_xor_sync(0xffffffffu, el[hh][hf], 1);
                el[hh][hf] += __shfl_xor_sync(0xffffffffu, el[hh][hf], 2);
                er_[hh][hf] += __shfl_xor_sync(0xffffffffu, er_[hh][hf], 1);
                er_[hh][hf] += __shfl_xor_sync(0xffffffffu, er_[hh][hf], 2);
            }
        // z1 stores
        if (r0 < NN) {
            float* p0 = g_z1 + (size_t)r0 * F1 + wn * 64 + c * 2;
#pragma unroll
            for (int nt = 0; nt < 8; nt++)
                *reinterpret_cast<float2*>(p0 + nt * 8) = make_float2(acc[mt][nt][0], acc[mt][nt][1]);
        }
        if (r1 < NN) {
            float* p1 = g_z1 + (size_t)r1 * F1 + wn * 64 + c * 2;
#pragma unroll
            for (int nt = 0; nt < 8; nt++)
                *reinterpret_cast<float2*>(p1 + nt * 8) = make_float2(acc[mt][nt][2], acc[mt][nt][3]);
        }
        if (c == 0) {
#pragma unroll
            for (int hh = 0; hh < 2; hh++) {
                int head = wn * 2 + hh;
                if (r0 < NN) { g_el1[r0 * NH1 + head] = el[hh][0]; g_er1[r0 * NH1 + head] = er_[hh][0]; }
                if (r1 < NN) { g_el1[r1 * NH1 + head] = el[hh][1]; g_er1[r1 * NH1 + head] = er_[hh][1]; }
            }
        }
    }
}

// ---------------- fused softmax+aggregation layer 1: block(256) per dst ----------------
__global__ __launch_bounds__(256) void agg1_kernel(const float* __restrict__ b1) {
    __shared__ int ssrc[CAP];
    __shared__ float ev[NH1][CAP];
    int dst = blockIdx.x;
    int tid = threadIdx.x;
    int lane = tid & 31;
    int h = tid >> 5;
    int s = g_rowptr[dst], e = g_rowptr[dst + 1];
    int deg = e - s;
    if (tid == 0) g_deg[dst] = 0;   // restore invariant for next call's count_kernel
    int dcap = deg < CAP ? deg : CAP;
    for (int i = tid; i < dcap; i += 256) ssrc[i] = g_srcs[s + i];
    __syncthreads();

    float erh = g_er1[dst * NH1 + h];

    // pass 1: logits + max (warp h handles head h)
    float mx = -1e30f;
    for (int i = lane; i < deg; i += 32) {
        int src = (i < CAP) ? ssrc[i] : g_srcs[s + i];
        float v = g_el1[src * NH1 + h] + erh;
        v = v > 0.f ? v : 0.2f * v;
        if (i < CAP) ev[h][i] = v;
        mx = fmaxf(mx, v);
    }
#pragma unroll
    for (int o = 16; o > 0; o >>= 1) mx = fmaxf(mx, __shfl_xor_sync(0xffffffffu, mx, o));

    // pass 2: exp + sum
    float sm = 0.f;
    for (int i = lane; i < deg; i += 32) {
        float v;
        if (i < CAP) v = ev[h][i];
        else {
            int src = g_srcs[s + i];
            v = g_el1[src * NH1 + h] + erh;
            v = v > 0.f ? v : 0.2f * v;
        }
        float x = __expf(v - mx);
        if (i < CAP) ev[h][i] = x;
        sm += x;
    }
#pragma unroll
    for (int o = 16; o > 0; o >>= 1) sm += __shfl_xor_sync(0xffffffffu, sm, o);
    float rden = sm > 0.f ? 1.f / sm : 0.f;
    __syncthreads();

    // pass 3: weighted aggregation (thread tid = feature column; its warp == its head)
    float acc = 0.f;
    int i = 0;
    int dn = dcap & ~3;
    for (; i < dn; i += 4) {
        int s0 = ssrc[i], s1 = ssrc[i + 1], s2 = ssrc[i + 2], s3 = ssrc[i + 3];
        float w0 = ev[h][i], w1 = ev[h][i + 1], w2 = ev[h][i + 2], w3 = ev[h][i + 3];
        float v0 = g_z1[(size_t)s0 * F1 + tid];
        float v1 = g_z1[(size_t)s1 * F1 + tid];
        float v2 = g_z1[(size_t)s2 * F1 + tid];
        float v3 = g_z1[(size_t)s3 * F1 + tid];
        acc = fmaf(w0, v0, acc); acc = fmaf(w1, v1, acc);
        acc = fmaf(w2, v2, acc); acc = fmaf(w3, v3, acc);
    }
    for (; i < deg; i++) {
        int src; float w;
        if (i < CAP) { src = ssrc[i]; w = ev[h][i]; }
        else {
            src = g_srcs[s + i];
            float v = g_el1[src * NH1 + h] + erh;
            v = v > 0.f ? v : 0.2f * v;
            w = __expf(v - mx);
        }
        acc = fmaf(w, g_z1[(size_t)src * F1 + tid], acc);
    }
    float o = acc * rden + b1[tid];
    g_h1[(size_t)dst * F1 + tid] = o > 0.f ? o : (__expf(o) - 1.f);
}

// ---------------- GEMM2: z2[NN,40] = h1[NN,256] @ W2[256,40], fused el2/er2 ----------------
__global__ __launch_bounds__(256) void gemm2_kernel(const float* __restrict__ W,
                                                    const float* __restrict__ al2,
                                                    const float* __restrict__ ar2) {
    __shared__ float Ws[F1][NOUT];  // 40 KB
    int tid = threadIdx.x;
    for (int i = tid; i < F1 * NOUT; i += 256) Ws[i / NOUT][i % NOUT] = W[i];
    __syncthreads();

    int r0 = blockIdx.x * 256 + (tid >> 2) * 4;
    int c0 = (tid & 3) * 10;
    float acc[4][10];
#pragma unroll
    for (int i = 0; i < 4; i++)
#pragma unroll
        for (int j = 0; j < 10; j++) acc[i][j] = 0.f;

    bool valid[4];
    const float* ap[4];
#pragma unroll
    for (int i = 0; i < 4; i++) {
        valid[i] = (r0 + i) < NN;
        ap[i] = g_h1 + (size_t)(valid[i] ? (r0 + i) : 0) * F1;
    }
    for (int k0 = 0; k0 < F1; k0 += 4) {
        float4 av[4];
#pragma unroll
        for (int i = 0; i < 4; i++)
            av[i] = valid[i] ? *reinterpret_cast<const float4*>(ap[i] + k0)
                             : make_float4(0.f, 0.f, 0.f, 0.f);
#pragma unroll
        for (int kk = 0; kk < 4; kk++) {
            float a[4];
#pragma unroll
            for (int i = 0; i < 4; i++) a[i] = reinterpret_cast<const float*>(&av[i])[kk];
#pragma unroll
            for (int j = 0; j < 10; j++) {
                float wv = Ws[k0 + kk][c0 + j];
#pragma unroll
                for (int i = 0; i < 4; i++) acc[i][j] += a[i] * wv;
            }
        }
    }

    float alv[10], arv[10];
#pragma unroll
    for (int j = 0; j < 10; j++) { alv[j] = al2[c0 + j]; arv[j] = ar2[c0 + j]; }
#pragma unroll
    for (int i = 0; i < 4; i++) {
        float pl = 0.f, pr = 0.f;
#pragma unroll
        for (int j = 0; j < 10; j++) { pl += acc[i][j] * alv[j]; pr += acc[i][j] * arv[j]; }
        pl += __shfl_xor_sync(0xffffffffu, pl, 1);
        pl += __shfl_xor_sync(0xffffffffu, pl, 2);
        pr += __shfl_xor_sync(0xffffffffu, pr, 1);
        pr += __shfl_xor_sync(0xffffffffu, pr, 2);
        int r = r0 + i;
        if (r < NN) {
            float* cp = g_z2 + (size_t)r * NOUT + c0;
#pragma unroll
            for (int j = 0; j < 10; j++) cp[j] = acc[i][j];
            if ((tid & 3) == 0) { g_el2[r] = pl; g_er2[r] = pr; }
        }
    }
}

// ---------------- fused softmax+aggregation layer 2 -> output ----------------
__global__ __launch_bounds__(64) void agg2_kernel(const float* __restrict__ b2,
                                                  float* __restrict__ out) {
    __shared__ int ssrc[CAP];
    __shared__ float ev[CAP];
    __shared__ float sh_mx, sh_rden;
    int dst = blockIdx.x;
    int tid = threadIdx.x;
    int lane = tid & 31;
    int s = g_rowptr[dst], e = g_rowptr[dst + 1];
    int deg = e - s;
    int dcap = deg < CAP ? deg : CAP;
    for (int i = tid; i < dcap; i += 64) ssrc[i] = g_srcs[s + i];
    __syncthreads();

    float erh = g_er2[dst];
    if (tid < 32) {
        float mx = -1e30f;
        for (int i = lane; i < deg; i += 32) {
            int src = (i < CAP) ? ssrc[i] : g_srcs[s + i];
            float v = g_el2[src] + erh;
            v = v > 0.f ? v : 0.2f * v;
            if (i < CAP) ev[i] = v;
            mx = fmaxf(mx, v);
        }
#pragma unroll
        for (int o = 16; o > 0; o >>= 1) mx = fmaxf(mx, __shfl_xor_sync(0xffffffffu, mx, o));
        float sm = 0.f;
        for (int i = lane; i < deg; i += 32) {
            float v;
            if (i < CAP) v = ev[i];
            else {
                int src = g_srcs[s + i];
                v = g_el2[src] + erh;
                v = v > 0.f ? v : 0.2f * v;
            }
            float x = __expf(v - mx);
            if (i < CAP) ev[i] = x;
            sm += x;
        }
#pragma unroll
        for (int o = 16; o > 0; o >>= 1) sm += __shfl_xor_sync(0xffffffffu, sm, o);
        if (lane == 0) {
            sh_mx = mx;
            sh_rden = sm > 0.f ? 1.f / sm : 0.f;
        }
    }
    __syncthreads();
    float mx = sh_mx, rden = sh_rden;

    if (tid < NOUT) {
        float acc = 0.f;
        int i = 0;
        int dn = dcap & ~3;
        for (; i < dn; i += 4) {
            int s0 = ssrc[i], s1 = ssrc[i + 1], s2 = ssrc[i + 2], s3 = ssrc[i + 3];
            float w0 = ev[i], w1 = ev[i + 1], w2 = ev[i + 2], w3 = ev[i + 3];
            float v0 = g_z2[(size_t)s0 * NOUT + tid];
            float v1 = g_z2[(size_t)s1 * NOUT + tid];
            float v2 = g_z2[(size_t)s2 * NOUT + tid];
            float v3 = g_z2[(size_t)s3 * NOUT + tid];
            acc = fmaf(w0, v0, acc); acc = fmaf(w1, v1, acc);
            acc = fmaf(w2, v2, acc); acc = fmaf(w3, v3, acc);
        }
        for (; i < deg; i++) {
            int src; float w;
            if (i < CAP) { src = ssrc[i]; w = ev[i]; }
            else {
                src = g_srcs[s + i];
                float v = g_el2[src] + erh;
                v = v > 0.f ? v : 0.2f * v;
                w = __expf(v - mx);
            }
            acc = fmaf(w, g_z2[(size_t)src * NOUT + tid], acc);
        }
        out[dst * NOUT + tid] = acc * rden + b2[tid];
    }
}

// ---------------- launch ----------------
extern "C" void kernel_launch(void* const* d_in, const int* in_sizes, int n_in,
                              void* d_out, int out_size) {
    const float* feat = (const float*)d_in[0];
    const int* src = (const int*)d_in[1];
    const int* dst = (const int*)d_in[2];
    const float* W1 = (const float*)d_in[3];
    const float* al1 = (const float*)d_in[4];
    const float* ar1 = (const float*)d_in[5];
    const float* b1 = (const float*)d_in[6];
    const float* W2 = (const float*)d_in[7];
    const float* al2 = (const float*)d_in[8];
    const float* ar2 = (const float*)d_in[9];
    const float* b2 = (const float*)d_in[10];
    float* out = (float*)d_out;

    cudaFuncSetAttribute(gemm1_kernel, cudaFuncAttributeMaxDynamicSharedMemorySize,
                         G1_SMEM_BYTES);

    // CSR by destination (g_deg zeroed by previous call's agg1 / static init)
    count_kernel<<<(NE + 255) / 256, 256>>>(dst);
    scan_kernel<<<1, 1024>>>();
    scatter_kernel<<<(NE + 255) / 256, 256>>>(src, dst);

    // layer 1
    gemm1_kernel<<<(NN + G1_BM - 1) / G1_BM, 256, G1_SMEM_BYTES>>>(feat, W1, al1, ar1);
    agg1_kernel<<<NN, 256>>>(b1);

    // layer 2
    gemm2_kernel<<<(NN + 255) / 256, 256>>>(W2, al2, ar2);
    agg2_kernel<<<NN, 64>>>(b2, out);
}

// round 6
// speedup vs baseline: 1.0699x; 1.0389x over previous
#include <cuda_runtime.h>
#include <cstdint>

#define NN   50000
#define NE   800000
#define FIN  128
#define NH1  8
#define HID  32
#define F1   256   // NH1*HID
#define NOUT 40
#define CAP  512   // smem edge cap per dst (max degree ~50 for Poisson(16); fallback is exact)

// GEMM1 tiling: block 128x128, warp 32x64, BK=32, double-buffered cp.async
#define G1_BM 128
#define G1_BN 128
#define G1_BK 32
#define G1_MTILES (((NN) + G1_BM - 1) / G1_BM)      // 391
#define G1_TILES (G1_MTILES * 2)                    // 782 (N=256 -> 2 col tiles)
#define CNT_BLOCKS ((NE + 255) / 256)               // 3125
#define AS_STRIDE 36    // 32 + 4 pad floats; 144B = 9*16
#define BS_STRIDE 132   // 128 + 4 pad floats; 528B = 33*16
#define AS_ELEMS (G1_BM * AS_STRIDE)                // 4608
#define BS_ELEMS (G1_BK * BS_STRIDE)                // 4224
#define G1_SMEM_BYTES ((2 * AS_ELEMS + 2 * BS_ELEMS) * 4)   // 70656

// ---------------- scratch (device globals; no allocation allowed) ----------------
__device__ float g_z1[(size_t)NN * F1];     // feat @ W1
__device__ float g_h1[(size_t)NN * F1];     // elu(agg1 + b1)
__device__ float g_z2[(size_t)NN * NOUT];   // h1 @ W2
__device__ float g_el1[NN * NH1];
__device__ float g_er1[NN * NH1];
__device__ float g_el2[NN];
__device__ float g_er2[NN];
__device__ int   g_deg[NN];                 // zeroed by agg1 each call (invariant)
__device__ int   g_cursor[NN];              // zeroed by scan each call
__device__ int   g_rowptr[NN + 1];
__device__ int   g_srcs[NE];                // src node per CSR slot

// ---------------- tf32 helpers ----------------
__device__ __forceinline__ uint32_t f2tf32(float x) {
    uint32_t r;
    asm("cvt.rna.tf32.f32 %0, %1;" : "=r"(r) : "f"(x));
    return r;
}
__device__ __forceinline__ void tf32_split(float x, uint32_t& hi, uint32_t& lo) {
    hi = f2tf32(x);
    lo = f2tf32(x - __uint_as_float(hi));
}
__device__ __forceinline__ void mma_tf32(float* d, const uint32_t* a, uint32_t b0, uint32_t b1) {
    asm volatile(
        "mma.sync.aligned.m16n8k8.row.col.f32.tf32.tf32.f32 "
        "{%0,%1,%2,%3},{%4,%5,%6,%7},{%8,%9},{%0,%1,%2,%3};"
        : "+f"(d[0]), "+f"(d[1]), "+f"(d[2]), "+f"(d[3])
        : "r"(a[0]), "r"(a[1]), "r"(a[2]), "r"(a[3]), "r"(b0), "r"(b1));
}
__device__ __forceinline__ void cpa16(uint32_t dst, const void* src, bool ok) {
    asm volatile("cp.async.cg.shared.global [%0], [%1], 16, %2;"
                 :: "r"(dst), "l"(src), "r"(ok ? 16 : 0));
}
__device__ __forceinline__ void cpa_commit() { asm volatile("cp.async.commit_group;"); }
template <int N>
__device__ __forceinline__ void cpa_wait() { asm volatile("cp.async.wait_group %0;" :: "n"(N)); }

// ---------------- GEMM1 (tf32 3-term) + fused edge-count histogram ----------------
// blocks [0, G1_TILES): GEMM tiles; blocks [G1_TILES, +CNT_BLOCKS): count dst histogram
__global__ __launch_bounds__(256, 2) void gemm1_kernel(const float* __restrict__ A,
                                                       const float* __restrict__ B,
                                                       const float* __restrict__ al,
                                                       const float* __restrict__ ar,
                                                       const int* __restrict__ dst) {
    int tid = threadIdx.x;
    if (blockIdx.x >= G1_TILES) {
        int e = (blockIdx.x - G1_TILES) * 256 + tid;
        if (e < NE) atomicAdd(&g_deg[dst[e]], 1);
        return;
    }

    extern __shared__ float smx[];
    float* Asm[2] = { smx, smx + AS_ELEMS };
    float* Bsm[2] = { smx + 2 * AS_ELEMS, smx + 2 * AS_ELEMS + BS_ELEMS };

    int wid = tid >> 5, lane = tid & 31;
    int wm = wid >> 1;          // 0..3 (32 rows each)
    int wn = wid & 1;           // 0..1 (64 cols each)
    int r = lane >> 2, c = lane & 3;
    int brow = (blockIdx.x >> 1) * G1_BM;
    int bcol = (blockIdx.x & 1) * G1_BN;

    // ---- cp.async mappings ----
    int la_row = tid >> 1;                 // 0..127
    int la_kq = (tid & 1) * 16;            // 0 or 16
    int la_gr = brow + la_row;
    bool la_ok = la_gr < NN;
    const float* la_src = A + (size_t)(la_ok ? la_gr : 0) * FIN + la_kq;
    int lb_row = tid >> 3;                 // 0..31
    int lb_col = (tid & 7) * 16;           // 0..112

    auto issue = [&](int kc, int buf) {
        uint32_t ad = (uint32_t)__cvta_generic_to_shared(Asm[buf] + la_row * AS_STRIDE + la_kq);
        const float* as = la_src + kc * G1_BK;
#pragma unroll
        for (int i = 0; i < 4; i++) cpa16(ad + i * 16, as + i * 4, la_ok);
        uint32_t bd = (uint32_t)__cvta_generic_to_shared(Bsm[buf] + lb_row * BS_STRIDE + lb_col);
        const float* bs = B + (size_t)(kc * G1_BK + lb_row) * F1 + bcol + lb_col;
#pragma unroll
        for (int i = 0; i < 4; i++) cpa16(bd + i * 16, bs + i * 4, true);
    };

    float acc[2][8][4];
#pragma unroll
    for (int mt = 0; mt < 2; mt++)
#pragma unroll
        for (int nt = 0; nt < 8; nt++)
#pragma unroll
            for (int j = 0; j < 4; j++) acc[mt][nt][j] = 0.f;

    issue(0, 0); cpa_commit();
    issue(1, 1); cpa_commit();
    cpa_wait<1>();
    __syncthreads();

#pragma unroll
    for (int kc = 0; kc < 4; kc++) {
        int buf = kc & 1;
        const float* as = Asm[buf];
        const float* bs = Bsm[buf];
#pragma unroll
        for (int ks = 0; ks < 4; ks++) {
            int k0 = ks * 8;
            uint32_t bh0[8], bl0[8], bh1[8], bl1[8];
            int bcl = wn * 64 + r;
#pragma unroll
            for (int nt = 0; nt < 8; nt++) {
                float b0 = bs[(k0 + c) * BS_STRIDE + bcl + nt * 8];
                float b1 = bs[(k0 + 4 + c) * BS_STRIDE + bcl + nt * 8];
                tf32_split(b0, bh0[nt], bl0[nt]);
                tf32_split(b1, bh1[nt], bl1[nt]);
            }
#pragma unroll
            for (int mt = 0; mt < 2; mt++) {
                int mr = wm * 32 + mt * 16 + r;
                float a0 = as[mr * AS_STRIDE + k0 + c];
                float a1 = as[(mr + 8) * AS_STRIDE + k0 + c];
                float a2 = as[mr * AS_STRIDE + k0 + 4 + c];
                float a3 = as[(mr + 8) * AS_STRIDE + k0 + 4 + c];
                uint32_t ah[4], alo[4];
                tf32_split(a0, ah[0], alo[0]);
                tf32_split(a1, ah[1], alo[1]);
                tf32_split(a2, ah[2], alo[2]);
                tf32_split(a3, ah[3], alo[3]);
#pragma unroll
                for (int nt = 0; nt < 8; nt++) {
                    mma_tf32(acc[mt][nt], ah, bh0[nt], bh1[nt]);
                    mma_tf32(acc[mt][nt], alo, bh0[nt], bh1[nt]);
                    mma_tf32(acc[mt][nt], ah, bl0[nt], bl1[nt]);
                }
            }
        }
        __syncthreads();
        if (kc == 0 || kc == 1) issue(kc + 2, buf);
        cpa_commit();
        if (kc < 3) {
            cpa_wait<1>();
            __syncthreads();
        }
    }

    // ---- epilogue: z1 store + fused el1/er1 ----
    float alv[16], arv[16];
#pragma unroll
    for (int nt = 0; nt < 8; nt++)
#pragma unroll
        for (int j = 0; j < 2; j++) {
            int head = (bcol >> 5) + wn * 2 + (nt >> 2);
            int cih = (nt & 3) * 8 + c * 2 + j;
            alv[nt * 2 + j] = al[head * HID + cih];
            arv[nt * 2 + j] = ar[head * HID + cih];
        }

#pragma unroll
    for (int mt = 0; mt < 2; mt++) {
        int r0 = brow + wm * 32 + mt * 16 + r;
        int r1 = r0 + 8;
        float el[2][2] = {{0.f, 0.f}, {0.f, 0.f}};
        float er_[2][2] = {{0.f, 0.f}, {0.f, 0.f}};
#pragma unroll
        for (int nt = 0; nt < 8; nt++) {
            int hh = nt >> 2;
#pragma unroll
            for (int j = 0; j < 2; j++) {
                float av = alv[nt * 2 + j], rv = arv[nt * 2 + j];
                el[hh][0] += acc[mt][nt][j] * av;
                er_[hh][0] += acc[mt][nt][j] * rv;
                el[hh][1] += acc[mt][nt][2 + j] * av;
                er_[hh][1] += acc[mt][nt][2 + j] * rv;
            }
        }
#pragma unroll
        for (int hh = 0; hh < 2; hh++)
#pragma unroll
            for (int hf = 0; hf < 2; hf++) {
                el[hh][hf] += __shfl_xor_sync(0xffffffffu, el[hh][hf], 1);
                el[hh][hf] += __shfl_xor_sync(0xffffffffu, el[hh][hf], 2);
                er_[hh][hf] += __shfl_xor_sync(0xffffffffu, er_[hh][hf], 1);
                er_[hh][hf] += __shfl_xor_sync(0xffffffffu, er_[hh][hf], 2);
            }
        if (r0 < NN) {
            float* p0 = g_z1 + (size_t)r0 * F1 + bcol + wn * 64 + c * 2;
#pragma unroll
            for (int nt = 0; nt < 8; nt++)
                *reinterpret_cast<float2*>(p0 + nt * 8) = make_float2(acc[mt][nt][0], acc[mt][nt][1]);
        }
        if (r1 < NN) {
            float* p1 = g_z1 + (size_t)r1 * F1 + bcol + wn * 64 + c * 2;
#pragma unroll
            for (int nt = 0; nt < 8; nt++)
                *reinterpret_cast<float2*>(p1 + nt * 8) = make_float2(acc[mt][nt][2], acc[mt][nt][3]);
        }
        if (c == 0) {
#pragma unroll
            for (int hh = 0; hh < 2; hh++) {
                int head = (bcol >> 5) + wn * 2 + hh;
                if (r0 < NN) { g_el1[r0 * NH1 + head] = el[hh][0]; g_er1[r0 * NH1 + head] = er_[hh][0]; }
                if (r1 < NN) { g_el1[r1 * NH1 + head] = el[hh][1]; g_er1[r1 * NH1 + head] = er_[hh][1]; }
            }
        }
    }
}

// ---------------- CSR: scan + scatter ----------------
__global__ void scan_kernel() {
    __shared__ int sums[1024];
    int tid = threadIdx.x;
    const int chunk = (NN + 1023) / 1024;
    int start = tid * chunk;
    int end = start + chunk; if (end > NN) end = NN;
    int local = 0;
    for (int i = start; i < end; i++) local += g_deg[i];
    sums[tid] = local;
    __syncthreads();
    for (int off = 1; off < 1024; off <<= 1) {
        int v = 0;
        if (tid >= off) v = sums[tid - off];
        __syncthreads();
        if (tid >= off) sums[tid] += v;
        __syncthreads();
    }
    int run = (tid == 0) ? 0 : sums[tid - 1];
    for (int i = start; i < end; i++) {
        g_rowptr[i] = run;
        run += g_deg[i];
        g_cursor[i] = 0;   // reset for scatter
    }
    if (tid == 1023) g_rowptr[NN] = run;
}

__global__ void scatter_kernel(const int* __restrict__ src, const int* __restrict__ dst) {
    int e = blockIdx.x * blockDim.x + threadIdx.x;
    if (e >= NE) return;
    int d = dst[e];
    int p = atomicAdd(&g_cursor[d], 1);
    g_srcs[g_rowptr[d] + p] = src[e];
}

// ---------------- fused softmax+aggregation layer 1: block(256) per dst ----------------
__global__ __launch_bounds__(256) void agg1_kernel(const float* __restrict__ b1) {
    __shared__ int ssrc[CAP];
    __shared__ float ev[NH1][CAP];
    int dst = blockIdx.x;
    int tid = threadIdx.x;
    int lane = tid & 31;
    int h = tid >> 5;
    int s = g_rowptr[dst], e = g_rowptr[dst + 1];
    int deg = e - s;
    if (tid == 0) g_deg[dst] = 0;   // restore invariant for next call's count
    int dcap = deg < CAP ? deg : CAP;
    for (int i = tid; i < dcap; i += 256) ssrc[i] = g_srcs[s + i];
    __syncthreads();

    float erh = g_er1[dst * NH1 + h];

    float mx = -1e30f;
    for (int i = lane; i < deg; i += 32) {
        int src = (i < CAP) ? ssrc[i] : g_srcs[s + i];
        float v = g_el1[src * NH1 + h] + erh;
        v = v > 0.f ? v : 0.2f * v;
        if (i < CAP) ev[h][i] = v;
        mx = fmaxf(mx, v);
    }
#pragma unroll
    for (int o = 16; o > 0; o >>= 1) mx = fmaxf(mx, __shfl_xor_sync(0xffffffffu, mx, o));

    float sm = 0.f;
    for (int i = lane; i < deg; i += 32) {
        float v;
        if (i < CAP) v = ev[h][i];
        else {
            int src = g_srcs[s + i];
            v = g_el1[src * NH1 + h] + erh;
            v = v > 0.f ? v : 0.2f * v;
        }
        float x = __expf(v - mx);
        if (i < CAP) ev[h][i] = x;
        sm += x;
    }
#pragma unroll
    for (int o = 16; o > 0; o >>= 1) sm += __shfl_xor_sync(0xffffffffu, sm, o);
    float rden = sm > 0.f ? 1.f / sm : 0.f;
    __syncthreads();

    float acc = 0.f;
    int i = 0;
    int dn = dcap & ~3;
    for (; i < dn; i += 4) {
        int s0 = ssrc[i], s1 = ssrc[i + 1], s2 = ssrc[i + 2], s3 = ssrc[i + 3];
        float w0 = ev[h][i], w1 = ev[h][i + 1], w2 = ev[h][i + 2], w3 = ev[h][i + 3];
        float v0 = g_z1[(size_t)s0 * F1 + tid];
        float v1 = g_z1[(size_t)s1 * F1 + tid];
        float v2 = g_z1[(size_t)s2 * F1 + tid];
        float v3 = g_z1[(size_t)s3 * F1 + tid];
        acc = fmaf(w0, v0, acc); acc = fmaf(w1, v1, acc);
        acc = fmaf(w2, v2, acc); acc = fmaf(w3, v3, acc);
    }
    for (; i < deg; i++) {
        int src; float w;
        if (i < CAP) { src = ssrc[i]; w = ev[h][i]; }
        else {
            src = g_srcs[s + i];
            float v = g_el1[src * NH1 + h] + erh;
            v = v > 0.f ? v : 0.2f * v;
            w = __expf(v - mx);
        }
        acc = fmaf(w, g_z1[(size_t)src * F1 + tid], acc);
    }
    float o = acc * rden + b1[tid];
    g_h1[(size_t)dst * F1 + tid] = o > 0.f ? o : (__expf(o) - 1.f);
}

// ---------------- GEMM2: z2[NN,40] = h1[NN,256] @ W2[256,40], fused el2/er2 ----------------
__global__ __launch_bounds__(256) void gemm2_kernel(const float* __restrict__ W,
                                                    const float* __restrict__ al2,
                                                    const float* __restrict__ ar2) {
    __shared__ float Ws[F1][NOUT];  // 40 KB
    int tid = threadIdx.x;
    for (int i = tid; i < F1 * NOUT; i += 256) Ws[i / NOUT][i % NOUT] = W[i];
    __syncthreads();

    int r0 = blockIdx.x * 256 + (tid >> 2) * 4;
    int c0 = (tid & 3) * 10;
    float acc[4][10];
#pragma unroll
    for (int i = 0; i < 4; i++)
#pragma unroll
        for (int j = 0; j < 10; j++) acc[i][j] = 0.f;

    bool valid[4];
    const float* ap[4];
#pragma unroll
    for (int i = 0; i < 4; i++) {
        valid[i] = (r0 + i) < NN;
        ap[i] = g_h1 + (size_t)(valid[i] ? (r0 + i) : 0) * F1;
    }
    for (int k0 = 0; k0 < F1; k0 += 4) {
        float4 av[4];
#pragma unroll
        for (int i = 0; i < 4; i++)
            av[i] = valid[i] ? *reinterpret_cast<const float4*>(ap[i] + k0)
                             : make_float4(0.f, 0.f, 0.f, 0.f);
#pragma unroll
        for (int kk = 0; kk < 4; kk++) {
            float a[4];
#pragma unroll
            for (int i = 0; i < 4; i++) a[i] = reinterpret_cast<const float*>(&av[i])[kk];
#pragma unroll
            for (int j = 0; j < 10; j++) {
                float wv = Ws[k0 + kk][c0 + j];
#pragma unroll
                for (int i = 0; i < 4; i++) acc[i][j] += a[i] * wv;
            }
        }
    }

    float alv[10], arv[10];
#pragma unroll
    for (int j = 0; j < 10; j++) { alv[j] = al2[c0 + j]; arv[j] = ar2[c0 + j]; }
#pragma unroll
    for (int i = 0; i < 4; i++) {
        float pl = 0.f, pr = 0.f;
#pragma unroll
        for (int j = 0; j < 10; j++) { pl += acc[i][j] * alv[j]; pr += acc[i][j] * arv[j]; }
        pl += __shfl_xor_sync(0xffffffffu, pl, 1);
        pl += __shfl_xor_sync(0xffffffffu, pl, 2);
        pr += __shfl_xor_sync(0xffffffffu, pr, 1);
        pr += __shfl_xor_sync(0xffffffffu, pr, 2);
        int r = r0 + i;
        if (r < NN) {
            float* cp = g_z2 + (size_t)r * NOUT + c0;
#pragma unroll
            for (int j = 0; j < 10; j++) cp[j] = acc[i][j];
            if ((tid & 3) == 0) { g_el2[r] = pl; g_er2[r] = pr; }
        }
    }
}

// ---------------- fused softmax+aggregation layer 2 -> output ----------------
__global__ __launch_bounds__(64) void agg2_kernel(const float* __restrict__ b2,
                                                  float* __restrict__ out) {
    __shared__ int ssrc[CAP];
    __shared__ float ev[CAP];
    __shared__ float sh_mx, sh_rden;
    int dst = blockIdx.x;
    int tid = threadIdx.x;
    int lane = tid & 31;
    int s = g_rowptr[dst], e = g_rowptr[dst + 1];
    int deg = e - s;
    int dcap = deg < CAP ? deg : CAP;
    for (int i = tid; i < dcap; i += 64) ssrc[i] = g_srcs[s + i];
    __syncthreads();

    float erh = g_er2[dst];
    if (tid < 32) {
        float mx = -1e30f;
        for (int i = lane; i < deg; i += 32) {
            int src = (i < CAP) ? ssrc[i] : g_srcs[s + i];
            float v = g_el2[src] + erh;
            v = v > 0.f ? v : 0.2f * v;
            if (i < CAP) ev[i] = v;
            mx = fmaxf(mx, v);
        }
#pragma unroll
        for (int o = 16; o > 0; o >>= 1) mx = fmaxf(mx, __shfl_xor_sync(0xffffffffu, mx, o));
        float sm = 0.f;
        for (int i = lane; i < deg; i += 32) {
            float v;
            if (i < CAP) v = ev[i];
            else {
                int src = g_srcs[s + i];
                v = g_el2[src] + erh;
                v = v > 0.f ? v : 0.2f * v;
            }
            float x = __expf(v - mx);
            if (i < CAP) ev[i] = x;
            sm += x;
        }
#pragma unroll
        for (int o = 16; o > 0; o >>= 1) sm += __shfl_xor_sync(0xffffffffu, sm, o);
        if (lane == 0) {
            sh_mx = mx;
            sh_rden = sm > 0.f ? 1.f / sm : 0.f;
        }
    }
    __syncthreads();
    float mx = sh_mx, rden = sh_rden;

    if (tid < NOUT) {
        float acc = 0.f;
        int i = 0;
        int dn = dcap & ~3;
        for (; i < dn; i += 4) {
            int s0 = ssrc[i], s1 = ssrc[i + 1], s2 = ssrc[i + 2], s3 = ssrc[i + 3];
            float w0 = ev[i], w1 = ev[i + 1], w2 = ev[i + 2], w3 = ev[i + 3];
            float v0 = g_z2[(size_t)s0 * NOUT + tid];
            float v1 = g_z2[(size_t)s1 * NOUT + tid];
            float v2 = g_z2[(size_t)s2 * NOUT + tid];
            float v3 = g_z2[(size_t)s3 * NOUT + tid];
            acc = fmaf(w0, v0, acc); acc = fmaf(w1, v1, acc);
            acc = fmaf(w2, v2, acc); acc = fmaf(w3, v3, acc);
        }
        for (; i < deg; i++) {
            int src; float w;
            if (i < CAP) { src = ssrc[i]; w = ev[i]; }
            else {
                src = g_srcs[s + i];
                float v = g_el2[src] + erh;
                v = v > 0.f ? v : 0.2f * v;
                w = __expf(v - mx);
            }
            acc = fmaf(w, g_z2[(size_t)src * NOUT + tid], acc);
        }
        out[dst * NOUT + tid] = acc * rden + b2[tid];
    }
}

// ---------------- launch ----------------
extern "C" void kernel_launch(void* const* d_in, const int* in_sizes, int n_in,
                              void* d_out, int out_size) {
    const float* feat = (const float*)d_in[0];
    const int* src = (const int*)d_in[1];
    const int* dst = (const int*)d_in[2];
    const float* W1 = (const float*)d_in[3];
    const float* al1 = (const float*)d_in[4];
    const float* ar1 = (const float*)d_in[5];
    const float* b1 = (const float*)d_in[6];
    const float* W2 = (const float*)d_in[7];
    const float* al2 = (const float*)d_in[8];
    const float* ar2 = (const float*)d_in[9];
    const float* b2 = (const float*)d_in[10];
    float* out = (float*)d_out;

    cudaFuncSetAttribute(gemm1_kernel, cudaFuncAttributeMaxDynamicSharedMemorySize,
                         G1_SMEM_BYTES);

    // (0) GEMM1 (+ fused dst-degree histogram)
    gemm1_kernel<<<G1_TILES + CNT_BLOCKS, 256, G1_SMEM_BYTES>>>(feat, W1, al1, ar1, dst);
    // (1) prefix sum, (2) CSR scatter
    scan_kernel<<<1, 1024>>>();
    scatter_kernel<<<(NE + 255) / 256, 256>>>(src, dst);
    // (3) layer-1 softmax+aggregate  <- profiled launch index
    agg1_kernel<<<NN, 256>>>(b1);
    // (4) layer-2 GEMM, (5) layer-2 softmax+aggregate
    gemm2_kernel<<<(NN + 255) / 256, 256>>>(W2, al2, ar2);
    agg2_kernel<<<NN, 64>>>(b2, out);
}

// round 7
// speedup vs baseline: 1.3329x; 1.2459x over previous
#include <cuda_runtime.h>
#include <cstdint>

#define NN   50000
#define NE   800000
#define FIN  128
#define NH1  8
#define HID  32
#define F1   256   // NH1*HID
#define NOUT 40
#define CAP  512   // agg2 smem cap
#define NDST 4     // dsts per agg1 block
#define CAP1 128   // agg1 per-dst smem edge cap (max degree ~50; fallback exact)
#define EVS  132   // ev stride (pad vs 128 to avoid same-bank broadcast conflicts)

// GEMM1 tiling: block 128x128, warp 32x64, BK=32, double-buffered cp.async
#define G1_BM 128
#define G1_BN 128
#define G1_BK 32
#define G1_MTILES (((NN) + G1_BM - 1) / G1_BM)      // 391
#define G1_TILES (G1_MTILES * 2)                    // 782
#define CNT_BLOCKS ((NE + 255) / 256)               // 3125
#define AS_STRIDE 36
#define BS_STRIDE 132
#define AS_ELEMS (G1_BM * AS_STRIDE)
#define BS_ELEMS (G1_BK * BS_STRIDE)
#define G1_SMEM_BYTES ((2 * AS_ELEMS + 2 * BS_ELEMS) * 4)   // 70656

// ---------------- scratch ----------------
__device__ float g_z1[(size_t)NN * F1];
__device__ float g_h1[(size_t)NN * F1];
__device__ float g_z2[(size_t)NN * NOUT];
__device__ float g_el1[NN * NH1];
__device__ float g_er1[NN * NH1];
__device__ float g_el2[NN];
__device__ float g_er2[NN];
__device__ int   g_deg[NN];
__device__ int   g_cursor[NN];
__device__ int   g_rowptr[NN + 1];
__device__ int   g_srcs[NE];

// ---------------- tf32 helpers ----------------
__device__ __forceinline__ uint32_t f2tf32(float x) {
    uint32_t r;
    asm("cvt.rna.tf32.f32 %0, %1;" : "=r"(r) : "f"(x));
    return r;
}
__device__ __forceinline__ void tf32_split(float x, uint32_t& hi, uint32_t& lo) {
    hi = f2tf32(x);
    lo = f2tf32(x - __uint_as_float(hi));
}
__device__ __forceinline__ void mma_tf32(float* d, const uint32_t* a, uint32_t b0, uint32_t b1) {
    asm volatile(
        "mma.sync.aligned.m16n8k8.row.col.f32.tf32.tf32.f32 "
        "{%0,%1,%2,%3},{%4,%5,%6,%7},{%8,%9},{%0,%1,%2,%3};"
        : "+f"(d[0]), "+f"(d[1]), "+f"(d[2]), "+f"(d[3])
        : "r"(a[0]), "r"(a[1]), "r"(a[2]), "r"(a[3]), "r"(b0), "r"(b1));
}
__device__ __forceinline__ void cpa16(uint32_t dst, const void* src, bool ok) {
    asm volatile("cp.async.cg.shared.global [%0], [%1], 16, %2;"
                 :: "r"(dst), "l"(src), "r"(ok ? 16 : 0));
}
__device__ __forceinline__ void cpa_commit() { asm volatile("cp.async.commit_group;"); }
template <int N>
__device__ __forceinline__ void cpa_wait() { asm volatile("cp.async.wait_group %0;" :: "n"(N)); }
__device__ __forceinline__ float lrelu(float v) { return v > 0.f ? v : 0.2f * v; }

// ---------------- GEMM1 (tf32 3-term) + fused edge-count histogram ----------------
__global__ __launch_bounds__(256, 2) void gemm1_kernel(const float* __restrict__ A,
                                                       const float* __restrict__ B,
                                                       const float* __restrict__ al,
                                                       const float* __restrict__ ar,
                                                       const int* __restrict__ dst) {
    int tid = threadIdx.x;
    if (blockIdx.x >= G1_TILES) {
        int e = (blockIdx.x - G1_TILES) * 256 + tid;
        if (e < NE) atomicAdd(&g_deg[dst[e]], 1);
        return;
    }

    extern __shared__ float smx[];
    float* Asm[2] = { smx, smx + AS_ELEMS };
    float* Bsm[2] = { smx + 2 * AS_ELEMS, smx + 2 * AS_ELEMS + BS_ELEMS };

    int wid = tid >> 5, lane = tid & 31;
    int wm = wid >> 1, wn = wid & 1;
    int r = lane >> 2, c = lane & 3;
    int brow = (blockIdx.x >> 1) * G1_BM;
    int bcol = (blockIdx.x & 1) * G1_BN;

    int la_row = tid >> 1;
    int la_kq = (tid & 1) * 16;
    int la_gr = brow + la_row;
    bool la_ok = la_gr < NN;
    const float* la_src = A + (size_t)(la_ok ? la_gr : 0) * FIN + la_kq;
    int lb_row = tid >> 3;
    int lb_col = (tid & 7) * 16;

    auto issue = [&](int kc, int buf) {
        uint32_t ad = (uint32_t)__cvta_generic_to_shared(Asm[buf] + la_row * AS_STRIDE + la_kq);
        const float* as = la_src + kc * G1_BK;
#pragma unroll
        for (int i = 0; i < 4; i++) cpa16(ad + i * 16, as + i * 4, la_ok);
        uint32_t bd = (uint32_t)__cvta_generic_to_shared(Bsm[buf] + lb_row * BS_STRIDE + lb_col);
        const float* bs = B + (size_t)(kc * G1_BK + lb_row) * F1 + bcol + lb_col;
#pragma unroll
        for (int i = 0; i < 4; i++) cpa16(bd + i * 16, bs + i * 4, true);
    };

    float acc[2][8][4];
#pragma unroll
    for (int mt = 0; mt < 2; mt++)
#pragma unroll
        for (int nt = 0; nt < 8; nt++)
#pragma unroll
            for (int j = 0; j < 4; j++) acc[mt][nt][j] = 0.f;

    issue(0, 0); cpa_commit();
    issue(1, 1); cpa_commit();
    cpa_wait<1>();
    __syncthreads();

#pragma unroll
    for (int kc = 0; kc < 4; kc++) {
        int buf = kc & 1;
        const float* as = Asm[buf];
        const float* bs = Bsm[buf];
#pragma unroll
        for (int ks = 0; ks < 4; ks++) {
            int k0 = ks * 8;
            uint32_t bh0[8], bl0[8], bh1[8], bl1[8];
            int bcl = wn * 64 + r;
#pragma unroll
            for (int nt = 0; nt < 8; nt++) {
                float b0 = bs[(k0 + c) * BS_STRIDE + bcl + nt * 8];
                float b1 = bs[(k0 + 4 + c) * BS_STRIDE + bcl + nt * 8];
                tf32_split(b0, bh0[nt], bl0[nt]);
                tf32_split(b1, bh1[nt], bl1[nt]);
            }
#pragma unroll
            for (int mt = 0; mt < 2; mt++) {
                int mr = wm * 32 + mt * 16 + r;
                float a0 = as[mr * AS_STRIDE + k0 + c];
                float a1 = as[(mr + 8) * AS_STRIDE + k0 + c];
                float a2 = as[mr * AS_STRIDE + k0 + 4 + c];
                float a3 = as[(mr + 8) * AS_STRIDE + k0 + 4 + c];
                uint32_t ah[4], alo[4];
                tf32_split(a0, ah[0], alo[0]);
                tf32_split(a1, ah[1], alo[1]);
                tf32_split(a2, ah[2], alo[2]);
                tf32_split(a3, ah[3], alo[3]);
#pragma unroll
                for (int nt = 0; nt < 8; nt++) {
                    mma_tf32(acc[mt][nt], ah, bh0[nt], bh1[nt]);
                    mma_tf32(acc[mt][nt], alo, bh0[nt], bh1[nt]);
                    mma_tf32(acc[mt][nt], ah, bl0[nt], bl1[nt]);
                }
            }
        }
        __syncthreads();
        if (kc == 0 || kc == 1) issue(kc + 2, buf);
        cpa_commit();
        if (kc < 3) {
            cpa_wait<1>();
            __syncthreads();
        }
    }

    float alv[16], arv[16];
#pragma unroll
    for (int nt = 0; nt < 8; nt++)
#pragma unroll
        for (int j = 0; j < 2; j++) {
            int head = (bcol >> 5) + wn * 2 + (nt >> 2);
            int cih = (nt & 3) * 8 + c * 2 + j;
            alv[nt * 2 + j] = al[head * HID + cih];
            arv[nt * 2 + j] = ar[head * HID + cih];
        }

#pragma unroll
    for (int mt = 0; mt < 2; mt++) {
        int r0 = brow + wm * 32 + mt * 16 + r;
        int r1 = r0 + 8;
        float el[2][2] = {{0.f, 0.f}, {0.f, 0.f}};
        float er_[2][2] = {{0.f, 0.f}, {0.f, 0.f}};
#pragma unroll
        for (int nt = 0; nt < 8; nt++) {
            int hh = nt >> 2;
#pragma unroll
            for (int j = 0; j < 2; j++) {
                float av = alv[nt * 2 + j], rv = arv[nt * 2 + j];
                el[hh][0] += acc[mt][nt][j] * av;
                er_[hh][0] += acc[mt][nt][j] * rv;
                el[hh][1] += acc[mt][nt][2 + j] * av;
                er_[hh][1] += acc[mt][nt][2 + j] * rv;
            }
        }
#pragma unroll
        for (int hh = 0; hh < 2; hh++)
#pragma unroll
            for (int hf = 0; hf < 2; hf++) {
                el[hh][hf] += __shfl_xor_sync(0xffffffffu, el[hh][hf], 1);
                el[hh][hf] += __shfl_xor_sync(0xffffffffu, el[hh][hf], 2);
                er_[hh][hf] += __shfl_xor_sync(0xffffffffu, er_[hh][hf], 1);
                er_[hh][hf] += __shfl_xor_sync(0xffffffffu, er_[hh][hf], 2);
            }
        if (r0 < NN) {
            float* p0 = g_z1 + (size_t)r0 * F1 + bcol + wn * 64 + c * 2;
#pragma unroll
            for (int nt = 0; nt < 8; nt++)
                *reinterpret_cast<float2*>(p0 + nt * 8) = make_float2(acc[mt][nt][0], acc[mt][nt][1]);
        }
        if (r1 < NN) {
            float* p1 = g_z1 + (size_t)r1 * F1 + bcol + wn * 64 + c * 2;
#pragma unroll
            for (int nt = 0; nt < 8; nt++)
                *reinterpret_cast<float2*>(p1 + nt * 8) = make_float2(acc[mt][nt][2], acc[mt][nt][3]);
        }
        if (c == 0) {
#pragma unroll
            for (int hh = 0; hh < 2; hh++) {
                int head = (bcol >> 5) + wn * 2 + hh;
                if (r0 < NN) { g_el1[r0 * NH1 + head] = el[hh][0]; g_er1[r0 * NH1 + head] = er_[hh][0]; }
                if (r1 < NN) { g_el1[r1 * NH1 + head] = el[hh][1]; g_er1[r1 * NH1 + head] = er_[hh][1]; }
            }
        }
    }
}

// ---------------- CSR: scan + scatter ----------------
__global__ void scan_kernel() {
    __shared__ int sums[1024];
    int tid = threadIdx.x;
    const int chunk = (NN + 1023) / 1024;
    int start = tid * chunk;
    int end = start + chunk; if (end > NN) end = NN;
    int local = 0;
    for (int i = start; i < end; i++) local += g_deg[i];
    sums[tid] = local;
    __syncthreads();
    for (int off = 1; off < 1024; off <<= 1) {
        int v = 0;
        if (tid >= off) v = sums[tid - off];
        __syncthreads();
        if (tid >= off) sums[tid] += v;
        __syncthreads();
    }
    int run = (tid == 0) ? 0 : sums[tid - 1];
    for (int i = start; i < end; i++) {
        g_rowptr[i] = run;
        run += g_deg[i];
        g_cursor[i] = 0;
    }
    if (tid == 1023) g_rowptr[NN] = run;
}

__global__ void scatter_kernel(const int* __restrict__ src, const int* __restrict__ dst) {
    int e = blockIdx.x * blockDim.x + threadIdx.x;
    if (e >= NE) return;
    int d = dst[e];
    int p = atomicAdd(&g_cursor[d], 1);
    g_srcs[g_rowptr[d] + p] = src[e];
}

// ---------------- fused softmax+aggregation layer 1: block = 4 dsts ----------------
__global__ __launch_bounds__(256) void agg1_kernel(const float* __restrict__ b1) {
    __shared__ int   soff[NDST][CAP1];         // src byte offsets (src*1024) into g_z1
    __shared__ float ev[NDST][NH1][EVS];       // exp weights
    __shared__ float s_rden[NDST][NH1];
    __shared__ float s_mxs[NDST][NH1];
    __shared__ int   s_s[NDST], s_deg[NDST];

    int tid = threadIdx.x, w = tid >> 5, lane = tid & 31;
    int d0 = blockIdx.x * NDST;

    if (tid < NDST) {
        int d = d0 + tid;
        int s = g_rowptr[d], e = g_rowptr[d + 1];
        s_s[tid] = s; s_deg[tid] = e - s;
        g_deg[d] = 0;   // restore invariant for next call's fused count
    }
    __syncthreads();

    if (w < NDST) {
        // softmax warp: all 8 heads of dst d0+w
        int g = w, d = d0 + g;
        int s = s_s[g], deg = s_deg[g];
        const float4* erv = reinterpret_cast<const float4*>(g_er1 + d * NH1);
        float4 er0 = erv[0], er1q = erv[1];
        float er[8] = {er0.x, er0.y, er0.z, er0.w, er1q.x, er1q.y, er1q.z, er1q.w};
        float mx[8];
#pragma unroll
        for (int k = 0; k < 8; k++) mx[k] = -1e30f;
        for (int i = lane; i < deg; i += 32) {
            int src = g_srcs[s + i];
            const float4* elv = reinterpret_cast<const float4*>(g_el1 + src * NH1);
            float4 e0 = elv[0], e1 = elv[1];
            float lg[8] = {lrelu(e0.x + er[0]), lrelu(e0.y + er[1]),
                           lrelu(e0.z + er[2]), lrelu(e0.w + er[3]),
                           lrelu(e1.x + er[4]), lrelu(e1.y + er[5]),
                           lrelu(e1.z + er[6]), lrelu(e1.w + er[7])};
            if (i < CAP1) {
#pragma unroll
                for (int k = 0; k < 8; k++) ev[g][k][i] = lg[k];
            }
#pragma unroll
            for (int k = 0; k < 8; k++) mx[k] = fmaxf(mx[k], lg[k]);
        }
#pragma unroll
        for (int k = 0; k < 8; k++)
#pragma unroll
            for (int o = 16; o > 0; o >>= 1) mx[k] = fmaxf(mx[k], __shfl_xor_sync(0xffffffffu, mx[k], o));

        float sm[8];
#pragma unroll
        for (int k = 0; k < 8; k++) sm[k] = 0.f;
        for (int i = lane; i < deg; i += 32) {
            float lg[8];
            if (i < CAP1) {
#pragma unroll
                for (int k = 0; k < 8; k++) lg[k] = ev[g][k][i];
            } else {
                int src = g_srcs[s + i];
                const float4* elv = reinterpret_cast<const float4*>(g_el1 + src * NH1);
                float4 e0 = elv[0], e1 = elv[1];
                lg[0] = lrelu(e0.x + er[0]); lg[1] = lrelu(e0.y + er[1]);
                lg[2] = lrelu(e0.z + er[2]); lg[3] = lrelu(e0.w + er[3]);
                lg[4] = lrelu(e1.x + er[4]); lg[5] = lrelu(e1.y + er[5]);
                lg[6] = lrelu(e1.z + er[6]); lg[7] = lrelu(e1.w + er[7]);
            }
#pragma unroll
            for (int k = 0; k < 8; k++) {
                float x = __expf(lg[k] - mx[k]);
                if (i < CAP1) ev[g][k][i] = x;
                sm[k] += x;
            }
        }
#pragma unroll
        for (int k = 0; k < 8; k++)
#pragma unroll
            for (int o = 16; o > 0; o >>= 1) sm[k] += __shfl_xor_sync(0xffffffffu, sm[k], o);
        if (lane == 0) {
#pragma unroll
            for (int k = 0; k < 8; k++) {
                s_rden[g][k] = sm[k] > 0.f ? 1.f / sm[k] : 0.f;
                s_mxs[g][k] = mx[k];
            }
        }
    } else {
        // offset-precompute warp for dst d0 + (w-NDST)
        int g = w - NDST;
        int s = s_s[g];
        int dc = s_deg[g] < CAP1 ? s_deg[g] : CAP1;
        for (int i = lane; i < dc; i += 32) soff[g][i] = g_srcs[s + i] << 10;  // *F1*4
    }
    __syncthreads();

    // aggregate: 64 threads per dst, float4 per thread
    int g = tid >> 6, t64 = tid & 63;
    int h = t64 >> 3;
    int d = d0 + g;
    int s = s_s[g], deg = s_deg[g];
    int dc = deg < CAP1 ? deg : CAP1;
    const char* zb = (const char*)g_z1 + t64 * 16;
    float4 acc = make_float4(0.f, 0.f, 0.f, 0.f);
    const float* evh = ev[g][h];
    int i = 0;
    int dn = dc & ~3;
    for (; i < dn; i += 4) {
        int o0 = soff[g][i], o1 = soff[g][i + 1], o2 = soff[g][i + 2], o3 = soff[g][i + 3];
        float w0 = evh[i], w1 = evh[i + 1], w2 = evh[i + 2], w3 = evh[i + 3];
        float4 v0 = *reinterpret_cast<const float4*>(zb + o0);
        float4 v1 = *reinterpret_cast<const float4*>(zb + o1);
        float4 v2 = *reinterpret_cast<const float4*>(zb + o2);
        float4 v3 = *reinterpret_cast<const float4*>(zb + o3);
        acc.x = fmaf(w0, v0.x, acc.x); acc.y = fmaf(w0, v0.y, acc.y);
        acc.z = fmaf(w0, v0.z, acc.z); acc.w = fmaf(w0, v0.w, acc.w);
        acc.x = fmaf(w1, v1.x, acc.x); acc.y = fmaf(w1, v1.y, acc.y);
        acc.z = fmaf(w1, v1.z, acc.z); acc.w = fmaf(w1, v1.w, acc.w);
        acc.x = fmaf(w2, v2.x, acc.x); acc.y = fmaf(w2, v2.y, acc.y);
        acc.z = fmaf(w2, v2.z, acc.z); acc.w = fmaf(w2, v2.w, acc.w);
        acc.x = fmaf(w3, v3.x, acc.x); acc.y = fmaf(w3, v3.y, acc.y);
        acc.z = fmaf(w3, v3.z, acc.z); acc.w = fmaf(w3, v3.w, acc.w);
    }
    for (; i < dc; i++) {
        int o0 = soff[g][i];
        float w0 = evh[i];
        float4 v0 = *reinterpret_cast<const float4*>(zb + o0);
        acc.x = fmaf(w0, v0.x, acc.x); acc.y = fmaf(w0, v0.y, acc.y);
        acc.z = fmaf(w0, v0.z, acc.z); acc.w = fmaf(w0, v0.w, acc.w);
    }
    if (deg > CAP1) {
        float erh = g_er1[d * NH1 + h];
        float mxh = s_mxs[g][h];
        for (i = CAP1; i < deg; i++) {
            int src = g_srcs[s + i];
            float wgt = __expf(lrelu(g_el1[src * NH1 + h] + erh) - mxh);
            float4 v0 = *reinterpret_cast<const float4*>(zb + (src << 10));
            acc.x = fmaf(wgt, v0.x, acc.x); acc.y = fmaf(wgt, v0.y, acc.y);
            acc.z = fmaf(wgt, v0.z, acc.z); acc.w = fmaf(wgt, v0.w, acc.w);
        }
    }
    float rden = s_rden[g][h];
    float4 bb = *reinterpret_cast<const float4*>(b1 + t64 * 4);
    float4 o;
    o.x = acc.x * rden + bb.x;
    o.y = acc.y * rden + bb.y;
    o.z = acc.z * rden + bb.z;
    o.w = acc.w * rden + bb.w;
    o.x = o.x > 0.f ? o.x : (__expf(o.x) - 1.f);
    o.y = o.y > 0.f ? o.y : (__expf(o.y) - 1.f);
    o.z = o.z > 0.f ? o.z : (__expf(o.z) - 1.f);
    o.w = o.w > 0.f ? o.w : (__expf(o.w) - 1.f);
    *reinterpret_cast<float4*>((char*)g_h1 + (size_t)d * 1024 + t64 * 16) = o;
}

// ---------------- GEMM2: z2[NN,40] = h1[NN,256] @ W2[256,40], fused el2/er2 ----------------
__global__ __launch_bounds__(256) void gemm2_kernel(const float* __restrict__ W,
                                                    const float* __restrict__ al2,
                                                    const float* __restrict__ ar2) {
    __shared__ float Ws[F1][NOUT];
    int tid = threadIdx.x;
    for (int i = tid; i < F1 * NOUT; i += 256) Ws[i / NOUT][i % NOUT] = W[i];
    __syncthreads();

    int r0 = blockIdx.x * 256 + (tid >> 2) * 4;
    int c0 = (tid & 3) * 10;
    float acc[4][10];
#pragma unroll
    for (int i = 0; i < 4; i++)
#pragma unroll
        for (int j = 0; j < 10; j++) acc[i][j] = 0.f;

    bool valid[4];
    const float* ap[4];
#pragma unroll
    for (int i = 0; i < 4; i++) {
        valid[i] = (r0 + i) < NN;
        ap[i] = g_h1 + (size_t)(valid[i] ? (r0 + i) : 0) * F1;
    }
    for (int k0 = 0; k0 < F1; k0 += 4) {
        float4 av[4];
#pragma unroll
        for (int i = 0; i < 4; i++)
            av[i] = valid[i] ? *reinterpret_cast<const float4*>(ap[i] + k0)
                             : make_float4(0.f, 0.f, 0.f, 0.f);
#pragma unroll
        for (int kk = 0; kk < 4; kk++) {
            float a[4];
#pragma unroll
            for (int i = 0; i < 4; i++) a[i] = reinterpret_cast<const float*>(&av[i])[kk];
#pragma unroll
            for (int j = 0; j < 10; j++) {
                float wv = Ws[k0 + kk][c0 + j];
#pragma unroll
                for (int i = 0; i < 4; i++) acc[i][j] += a[i] * wv;
            }
        }
    }

    float alv[10], arv[10];
#pragma unroll
    for (int j = 0; j < 10; j++) { alv[j] = al2[c0 + j]; arv[j] = ar2[c0 + j]; }
#pragma unroll
    for (int i = 0; i < 4; i++) {
        float pl = 0.f, pr = 0.f;
#pragma unroll
        for (int j = 0; j < 10; j++) { pl += acc[i][j] * alv[j]; pr += acc[i][j] * arv[j]; }
        pl += __shfl_xor_sync(0xffffffffu, pl, 1);
        pl += __shfl_xor_sync(0xffffffffu, pl, 2);
        pr += __shfl_xor_sync(0xffffffffu, pr, 1);
        pr += __shfl_xor_sync(0xffffffffu, pr, 2);
        int r = r0 + i;
        if (r < NN) {
            float* cp = g_z2 + (size_t)r * NOUT + c0;
#pragma unroll
            for (int j = 0; j < 10; j++) cp[j] = acc[i][j];
            if ((tid & 3) == 0) { g_el2[r] = pl; g_er2[r] = pr; }
        }
    }
}

// ---------------- fused softmax+aggregation layer 2 -> output ----------------
__global__ __launch_bounds__(64) void agg2_kernel(const float* __restrict__ b2,
                                                  float* __restrict__ out) {
    __shared__ int ssrc[CAP];
    __shared__ float ev2[CAP];
    __shared__ float sh_mx, sh_rden;
    int dst = blockIdx.x;
    int tid = threadIdx.x;
    int lane = tid & 31;
    int s = g_rowptr[dst], e = g_rowptr[dst + 1];
    int deg = e - s;
    int dcap = deg < CAP ? deg : CAP;
    for (int i = tid; i < dcap; i += 64) ssrc[i] = g_srcs[s + i];
    __syncthreads();

    float erh = g_er2[dst];
    if (tid < 32) {
        float mx = -1e30f;
        for (int i = lane; i < deg; i += 32) {
            int src = (i < CAP) ? ssrc[i] : g_srcs[s + i];
            float v = lrelu(g_el2[src] + erh);
            if (i < CAP) ev2[i] = v;
            mx = fmaxf(mx, v);
        }
#pragma unroll
        for (int o = 16; o > 0; o >>= 1) mx = fmaxf(mx, __shfl_xor_sync(0xffffffffu, mx, o));
        float sm = 0.f;
        for (int i = lane; i < deg; i += 32) {
            float v;
            if (i < CAP) v = ev2[i];
            else v = lrelu(g_el2[g_srcs[s + i]] + erh);
            float x = __expf(v - mx);
            if (i < CAP) ev2[i] = x;
            sm += x;
        }
#pragma unroll
        for (int o = 16; o > 0; o >>= 1) sm += __shfl_xor_sync(0xffffffffu, sm, o);
        if (lane == 0) {
            sh_mx = mx;
            sh_rden = sm > 0.f ? 1.f / sm : 0.f;
        }
    }
    __syncthreads();
    float mx = sh_mx, rden = sh_rden;

    if (tid < NOUT) {
        float acc = 0.f;
        int i = 0;
        int dn = dcap & ~3;
        for (; i < dn; i += 4) {
            int s0 = ssrc[i], s1 = ssrc[i + 1], s2 = ssrc[i + 2], s3 = ssrc[i + 3];
            float w0 = ev2[i], w1 = ev2[i + 1], w2 = ev2[i + 2], w3 = ev2[i + 3];
            float v0 = g_z2[(size_t)s0 * NOUT + tid];
            float v1 = g_z2[(size_t)s1 * NOUT + tid];
            float v2 = g_z2[(size_t)s2 * NOUT + tid];
            float v3 = g_z2[(size_t)s3 * NOUT + tid];
            acc = fmaf(w0, v0, acc); acc = fmaf(w1, v1, acc);
            acc = fmaf(w2, v2, acc); acc = fmaf(w3, v3, acc);
        }
        for (; i < deg; i++) {
            int src; float w;
            if (i < CAP) { src = ssrc[i]; w = ev2[i]; }
            else {
                src = g_srcs[s + i];
                w = __expf(lrelu(g_el2[src] + erh) - mx);
            }
            acc = fmaf(w, g_z2[(size_t)src * NOUT + tid], acc);
        }
        out[dst * NOUT + tid] = acc * rden + b2[tid];
    }
}

// ---------------- launch ----------------
extern "C" void kernel_launch(void* const* d_in, const int* in_sizes, int n_in,
                              void* d_out, int out_size) {
    const float* feat = (const float*)d_in[0];
    const int* src = (const int*)d_in[1];
    const int* dst = (const int*)d_in[2];
    const float* W1 = (const float*)d_in[3];
    const float* al1 = (const float*)d_in[4];
    const float* ar1 = (const float*)d_in[5];
    const float* b1 = (const float*)d_in[6];
    const float* W2 = (const float*)d_in[7];
    const float* al2 = (const float*)d_in[8];
    const float* ar2 = (const float*)d_in[9];
    const float* b2 = (const float*)d_in[10];
    float* out = (float*)d_out;

    cudaFuncSetAttribute(gemm1_kernel, cudaFuncAttributeMaxDynamicSharedMemorySize,
                         G1_SMEM_BYTES);

    // (0) GEMM1 (+ fused dst-degree histogram)
    gemm1_kernel<<<G1_TILES + CNT_BLOCKS, 256, G1_SMEM_BYTES>>>(feat, W1, al1, ar1, dst);
    // (1) prefix sum, (2) CSR scatter
    scan_kernel<<<1, 1024>>>();
    scatter_kernel<<<(NE + 255) / 256, 256>>>(src, dst);
    // (3) layer-1 softmax+aggregate  <- profiled launch index
    agg1_kernel<<<NN / NDST, 256>>>(b1);
    // (4) layer-2 GEMM, (5) layer-2 softmax+aggregate
    gemm2_kernel<<<(NN + 255) / 256, 256>>>(W2, al2, ar2);
    agg2_kernel<<<NN, 64>>>(b2, out);
}

// round 8
// speedup vs baseline: 1.5924x; 1.1947x over previous
#include <cuda_runtime.h>
#include <cuda_fp16.h>
#include <cstdint>

#define NN   50000
#define NE   800000
#define FIN  128
#define NH1  8
#define HID  32
#define F1   256   // NH1*HID
#define NOUT 40
#define NDST 8     // dsts per agg block (warp-per-dst)
#define CAP1 64    // per-dst smem edge cap (max degree ~50 for Poisson(16); fallback exact)
#define EVS  68    // ev stride (bank spacing 4 -> conflict-free across 8 heads)
#define CAP2 64

// GEMM1 tiling: block 128x128, warp 32x64, BK=32, double-buffered cp.async
#define G1_BM 128
#define G1_BN 128
#define G1_BK 32
#define G1_MTILES (((NN) + G1_BM - 1) / G1_BM)      // 391
#define G1_TILES (G1_MTILES * 2)                    // 782
#define CNT_BLOCKS ((NE + 255) / 256)               // 3125
#define AS_STRIDE 36
#define BS_STRIDE 132
#define AS_ELEMS (G1_BM * AS_STRIDE)
#define BS_ELEMS (G1_BK * BS_STRIDE)
#define G1_SMEM_BYTES ((2 * AS_ELEMS + 2 * BS_ELEMS) * 4)   // 70656

// ---------------- scratch ----------------
__device__ __half g_z1h[(size_t)NN * F1];   // feat @ W1, fp16 (consumed only by agg1 gather)
__device__ float g_h1[(size_t)NN * F1];
__device__ float g_z2[(size_t)NN * NOUT];
__device__ float g_el1[NN * NH1];
__device__ float g_er1[NN * NH1];
__device__ float g_el2[NN];
__device__ float g_er2[NN];
__device__ int   g_deg[NN];
__device__ int   g_cursor[NN];
__device__ int   g_rowptr[NN + 1];
__device__ int   g_srcs[NE];

// ---------------- helpers ----------------
__device__ __forceinline__ uint32_t f2tf32(float x) {
    uint32_t r;
    asm("cvt.rna.tf32.f32 %0, %1;" : "=r"(r) : "f"(x));
    return r;
}
__device__ __forceinline__ void tf32_split(float x, uint32_t& hi, uint32_t& lo) {
    hi = f2tf32(x);
    lo = f2tf32(x - __uint_as_float(hi));
}
__device__ __forceinline__ void mma_tf32(float* d, const uint32_t* a, uint32_t b0, uint32_t b1) {
    asm volatile(
        "mma.sync.aligned.m16n8k8.row.col.f32.tf32.tf32.f32 "
        "{%0,%1,%2,%3},{%4,%5,%6,%7},{%8,%9},{%0,%1,%2,%3};"
        : "+f"(d[0]), "+f"(d[1]), "+f"(d[2]), "+f"(d[3])
        : "r"(a[0]), "r"(a[1]), "r"(a[2]), "r"(a[3]), "r"(b0), "r"(b1));
}
__device__ __forceinline__ void cpa16(uint32_t dst, const void* src, bool ok) {
    asm volatile("cp.async.cg.shared.global [%0], [%1], 16, %2;"
                 :: "r"(dst), "l"(src), "r"(ok ? 16 : 0));
}
__device__ __forceinline__ void cpa_commit() { asm volatile("cp.async.commit_group;"); }
template <int N>
__device__ __forceinline__ void cpa_wait() { asm volatile("cp.async.wait_group %0;" :: "n"(N)); }
__device__ __forceinline__ float lrelu(float v) { return v > 0.f ? v : 0.2f * v; }

// ---------------- GEMM1 (tf32 3-term) + fused edge-count histogram ----------------
__global__ __launch_bounds__(256, 2) void gemm1_kernel(const float* __restrict__ A,
                                                       const float* __restrict__ B,
                                                       const float* __restrict__ al,
                                                       const float* __restrict__ ar,
                                                       const int* __restrict__ dst) {
    int tid = threadIdx.x;
    if (blockIdx.x >= G1_TILES) {
        int e = (blockIdx.x - G1_TILES) * 256 + tid;
        if (e < NE) atomicAdd(&g_deg[dst[e]], 1);
        return;
    }

    extern __shared__ float smx[];
    float* Asm[2] = { smx, smx + AS_ELEMS };
    float* Bsm[2] = { smx + 2 * AS_ELEMS, smx + 2 * AS_ELEMS + BS_ELEMS };

    int wid = tid >> 5, lane = tid & 31;
    int wm = wid >> 1, wn = wid & 1;
    int r = lane >> 2, c = lane & 3;
    int brow = (blockIdx.x >> 1) * G1_BM;
    int bcol = (blockIdx.x & 1) * G1_BN;

    int la_row = tid >> 1;
    int la_kq = (tid & 1) * 16;
    int la_gr = brow + la_row;
    bool la_ok = la_gr < NN;
    const float* la_src = A + (size_t)(la_ok ? la_gr : 0) * FIN + la_kq;
    int lb_row = tid >> 3;
    int lb_col = (tid & 7) * 16;

    auto issue = [&](int kc, int buf) {
        uint32_t ad = (uint32_t)__cvta_generic_to_shared(Asm[buf] + la_row * AS_STRIDE + la_kq);
        const float* as = la_src + kc * G1_BK;
#pragma unroll
        for (int i = 0; i < 4; i++) cpa16(ad + i * 16, as + i * 4, la_ok);
        uint32_t bd = (uint32_t)__cvta_generic_to_shared(Bsm[buf] + lb_row * BS_STRIDE + lb_col);
        const float* bs = B + (size_t)(kc * G1_BK + lb_row) * F1 + bcol + lb_col;
#pragma unroll
        for (int i = 0; i < 4; i++) cpa16(bd + i * 16, bs + i * 4, true);
    };

    float acc[2][8][4];
#pragma unroll
    for (int mt = 0; mt < 2; mt++)
#pragma unroll
        for (int nt = 0; nt < 8; nt++)
#pragma unroll
            for (int j = 0; j < 4; j++) acc[mt][nt][j] = 0.f;

    issue(0, 0); cpa_commit();
    issue(1, 1); cpa_commit();
    cpa_wait<1>();
    __syncthreads();

#pragma unroll
    for (int kc = 0; kc < 4; kc++) {
        int buf = kc & 1;
        const float* as = Asm[buf];
        const float* bs = Bsm[buf];
#pragma unroll
        for (int ks = 0; ks < 4; ks++) {
            int k0 = ks * 8;
            uint32_t bh0[8], bl0[8], bh1[8], bl1[8];
            int bcl = wn * 64 + r;
#pragma unroll
            for (int nt = 0; nt < 8; nt++) {
                float b0 = bs[(k0 + c) * BS_STRIDE + bcl + nt * 8];
                float b1 = bs[(k0 + 4 + c) * BS_STRIDE + bcl + nt * 8];
                tf32_split(b0, bh0[nt], bl0[nt]);
                tf32_split(b1, bh1[nt], bl1[nt]);
            }
#pragma unroll
            for (int mt = 0; mt < 2; mt++) {
                int mr = wm * 32 + mt * 16 + r;
                float a0 = as[mr * AS_STRIDE + k0 + c];
                float a1 = as[(mr + 8) * AS_STRIDE + k0 + c];
                float a2 = as[mr * AS_STRIDE + k0 + 4 + c];
                float a3 = as[(mr + 8) * AS_STRIDE + k0 + 4 + c];
                uint32_t ah[4], alo[4];
                tf32_split(a0, ah[0], alo[0]);
                tf32_split(a1, ah[1], alo[1]);
                tf32_split(a2, ah[2], alo[2]);
                tf32_split(a3, ah[3], alo[3]);
#pragma unroll
                for (int nt = 0; nt < 8; nt++) {
                    mma_tf32(acc[mt][nt], ah, bh0[nt], bh1[nt]);
                    mma_tf32(acc[mt][nt], alo, bh0[nt], bh1[nt]);
                    mma_tf32(acc[mt][nt], ah, bl0[nt], bl1[nt]);
                }
            }
        }
        __syncthreads();
        if (kc == 0 || kc == 1) issue(kc + 2, buf);
        cpa_commit();
        if (kc < 3) {
            cpa_wait<1>();
            __syncthreads();
        }
    }

    float alv[16], arv[16];
#pragma unroll
    for (int nt = 0; nt < 8; nt++)
#pragma unroll
        for (int j = 0; j < 2; j++) {
            int head = (bcol >> 5) + wn * 2 + (nt >> 2);
            int cih = (nt & 3) * 8 + c * 2 + j;
            alv[nt * 2 + j] = al[head * HID + cih];
            arv[nt * 2 + j] = ar[head * HID + cih];
        }

#pragma unroll
    for (int mt = 0; mt < 2; mt++) {
        int r0 = brow + wm * 32 + mt * 16 + r;
        int r1 = r0 + 8;
        float el[2][2] = {{0.f, 0.f}, {0.f, 0.f}};
        float er_[2][2] = {{0.f, 0.f}, {0.f, 0.f}};
#pragma unroll
        for (int nt = 0; nt < 8; nt++) {
            int hh = nt >> 2;
#pragma unroll
            for (int j = 0; j < 2; j++) {
                float av = alv[nt * 2 + j], rv = arv[nt * 2 + j];
                el[hh][0] += acc[mt][nt][j] * av;
                er_[hh][0] += acc[mt][nt][j] * rv;
                el[hh][1] += acc[mt][nt][2 + j] * av;
                er_[hh][1] += acc[mt][nt][2 + j] * rv;
            }
        }
#pragma unroll
        for (int hh = 0; hh < 2; hh++)
#pragma unroll
            for (int hf = 0; hf < 2; hf++) {
                el[hh][hf] += __shfl_xor_sync(0xffffffffu, el[hh][hf], 1);
                el[hh][hf] += __shfl_xor_sync(0xffffffffu, el[hh][hf], 2);
                er_[hh][hf] += __shfl_xor_sync(0xffffffffu, er_[hh][hf], 1);
                er_[hh][hf] += __shfl_xor_sync(0xffffffffu, er_[hh][hf], 2);
            }
        if (r0 < NN) {
            __half* p0 = g_z1h + (size_t)r0 * F1 + bcol + wn * 64 + c * 2;
#pragma unroll
            for (int nt = 0; nt < 8; nt++)
                *reinterpret_cast<__half2*>(p0 + nt * 8) = __floats2half2_rn(acc[mt][nt][0], acc[mt][nt][1]);
        }
        if (r1 < NN) {
            __half* p1 = g_z1h + (size_t)r1 * F1 + bcol + wn * 64 + c * 2;
#pragma unroll
            for (int nt = 0; nt < 8; nt++)
                *reinterpret_cast<__half2*>(p1 + nt * 8) = __floats2half2_rn(acc[mt][nt][2], acc[mt][nt][3]);
        }
        if (c == 0) {
#pragma unroll
            for (int hh = 0; hh < 2; hh++) {
                int head = (bcol >> 5) + wn * 2 + hh;
                if (r0 < NN) { g_el1[r0 * NH1 + head] = el[hh][0]; g_er1[r0 * NH1 + head] = er_[hh][0]; }
                if (r1 < NN) { g_el1[r1 * NH1 + head] = el[hh][1]; g_er1[r1 * NH1 + head] = er_[hh][1]; }
            }
        }
    }
}

// ---------------- CSR: scan + scatter ----------------
__global__ void scan_kernel() {
    __shared__ int sums[1024];
    int tid = threadIdx.x;
    const int chunk = (NN + 1023) / 1024;
    int start = tid * chunk;
    int end = start + chunk; if (end > NN) end = NN;
    int local = 0;
    for (int i = start; i < end; i++) local += g_deg[i];
    sums[tid] = local;
    __syncthreads();
    for (int off = 1; off < 1024; off <<= 1) {
        int v = 0;
        if (tid >= off) v = sums[tid - off];
        __syncthreads();
        if (tid >= off) sums[tid] += v;
        __syncthreads();
    }
    int run = (tid == 0) ? 0 : sums[tid - 1];
    for (int i = start; i < end; i++) {
        g_rowptr[i] = run;
        run += g_deg[i];
        g_cursor[i] = 0;
    }
    if (tid == 1023) g_rowptr[NN] = run;
}

__global__ void scatter_kernel(const int* __restrict__ src, const int* __restrict__ dst) {
    int e = blockIdx.x * blockDim.x + threadIdx.x;
    if (e >= NE) return;
    int d = dst[e];
    int p = atomicAdd(&g_cursor[d], 1);
    g_srcs[g_rowptr[d] + p] = src[e];
}

// ---------------- fused softmax+aggregation layer 1: warp per dst, 8 dsts/block ----------------
__global__ __launch_bounds__(256) void agg1_kernel(const float* __restrict__ b1) {
    __shared__ int   soff[NDST][CAP1];       // src byte offsets (src*512) into g_z1h
    __shared__ float ev[NDST][NH1][EVS];     // exp weights
    __shared__ float s_rden[NDST][NH1];
    __shared__ int   s_s[NDST], s_deg[NDST];

    int tid = threadIdx.x, w = tid >> 5, lane = tid & 31;
    int d0 = blockIdx.x * NDST;

    if (tid < NDST) {
        int d = d0 + tid;
        int s = g_rowptr[d];
        s_s[tid] = s; s_deg[tid] = g_rowptr[d + 1] - s;
        g_deg[d] = 0;   // restore invariant for next call's fused count
    }
    __syncthreads();

    // phase 1: warp w = single-pass softmax for dst d0+w (all 8 heads)
    {
        int g = w, d = d0 + g;
        int s = s_s[g], deg = s_deg[g];
        const float4* erv = reinterpret_cast<const float4*>(g_er1 + d * NH1);
        float4 er0 = erv[0], er1q = erv[1];
        float er[8] = {er0.x, er0.y, er0.z, er0.w, er1q.x, er1q.y, er1q.z, er1q.w};
        float sm[8];
#pragma unroll
        for (int k = 0; k < 8; k++) sm[k] = 0.f;
        for (int i = lane; i < deg; i += 32) {
            int src = g_srcs[s + i];
            const float4* elv = reinterpret_cast<const float4*>(g_el1 + src * NH1);
            float4 e0 = elv[0], e1 = elv[1];
            float x[8] = {__expf(lrelu(e0.x + er[0])), __expf(lrelu(e0.y + er[1])),
                          __expf(lrelu(e0.z + er[2])), __expf(lrelu(e0.w + er[3])),
                          __expf(lrelu(e1.x + er[4])), __expf(lrelu(e1.y + er[5])),
                          __expf(lrelu(e1.z + er[6])), __expf(lrelu(e1.w + er[7]))};
            if (i < CAP1) {
#pragma unroll
                for (int k = 0; k < 8; k++) ev[g][k][i] = x[k];
                soff[g][i] = src << 9;   // *F1*sizeof(half)
            }
#pragma unroll
            for (int k = 0; k < 8; k++) sm[k] += x[k];
        }
#pragma unroll
        for (int k = 0; k < 8; k++)
#pragma unroll
            for (int o = 16; o > 0; o >>= 1) sm[k] += __shfl_xor_sync(0xffffffffu, sm[k], o);
        if (lane == 0) {
#pragma unroll
            for (int k = 0; k < 8; k++) s_rden[g][k] = sm[k] > 0.f ? 1.f / sm[k] : 0.f;
        }
    }
    __syncthreads();

    // phase 2: warp w aggregates dst d0+w; lane owns 8 half features (16B)
    int g = w, d = d0 + g;
    int s = s_s[g], deg = s_deg[g];
    int dc = deg < CAP1 ? deg : CAP1;
    int h = lane >> 2;
    const char* zb = (const char*)g_z1h + lane * 16;
    const float* evh = ev[g][h];
    const int* sof = soff[g];
    float acc[8];
#pragma unroll
    for (int k = 0; k < 8; k++) acc[k] = 0.f;

    int i = 0;
    int dn = dc & ~3;
    for (; i < dn; i += 4) {
        int o0 = sof[i], o1 = sof[i + 1], o2 = sof[i + 2], o3 = sof[i + 3];
        float w0 = evh[i], w1 = evh[i + 1], w2 = evh[i + 2], w3 = evh[i + 3];
        uint4 v0 = *reinterpret_cast<const uint4*>(zb + o0);
        uint4 v1 = *reinterpret_cast<const uint4*>(zb + o1);
        uint4 v2 = *reinterpret_cast<const uint4*>(zb + o2);
        uint4 v3 = *reinterpret_cast<const uint4*>(zb + o3);
#pragma unroll
        for (int q = 0; q < 4; q++) {
            uint32_t u0 = (&v0.x)[q], u1 = (&v1.x)[q], u2 = (&v2.x)[q], u3 = (&v3.x)[q];
            float2 f0 = __half22float2(*reinterpret_cast<__half2*>(&u0));
            float2 f1 = __half22float2(*reinterpret_cast<__half2*>(&u1));
            float2 f2 = __half22float2(*reinterpret_cast<__half2*>(&u2));
            float2 f3 = __half22float2(*reinterpret_cast<__half2*>(&u3));
            acc[q * 2]     = fmaf(w0, f0.x, acc[q * 2]);
            acc[q * 2 + 1] = fmaf(w0, f0.y, acc[q * 2 + 1]);
            acc[q * 2]     = fmaf(w1, f1.x, acc[q * 2]);
            acc[q * 2 + 1] = fmaf(w1, f1.y, acc[q * 2 + 1]);
            acc[q * 2]     = fmaf(w2, f2.x, acc[q * 2]);
            acc[q * 2 + 1] = fmaf(w2, f2.y, acc[q * 2 + 1]);
            acc[q * 2]     = fmaf(w3, f3.x, acc[q * 2]);
            acc[q * 2 + 1] = fmaf(w3, f3.y, acc[q * 2 + 1]);
        }
    }
    for (; i < dc; i++) {
        int o0 = sof[i];
        float w0 = evh[i];
        uint4 v0 = *reinterpret_cast<const uint4*>(zb + o0);
#pragma unroll
        for (int q = 0; q < 4; q++) {
            uint32_t u0 = (&v0.x)[q];
            float2 f0 = __half22float2(*reinterpret_cast<__half2*>(&u0));
            acc[q * 2]     = fmaf(w0, f0.x, acc[q * 2]);
            acc[q * 2 + 1] = fmaf(w0, f0.y, acc[q * 2 + 1]);
        }
    }
    if (deg > CAP1) {
        float erh = g_er1[d * NH1 + h];
        for (i = CAP1; i < deg; i++) {
            int src = g_srcs[s + i];
            float wgt = __expf(lrelu(g_el1[src * NH1 + h] + erh));
            uint4 v0 = *reinterpret_cast<const uint4*>(zb + (src << 9));
#pragma unroll
            for (int q = 0; q < 4; q++) {
                uint32_t u0 = (&v0.x)[q];
                float2 f0 = __half22float2(*reinterpret_cast<__half2*>(&u0));
                acc[q * 2]     = fmaf(wgt, f0.x, acc[q * 2]);
                acc[q * 2 + 1] = fmaf(wgt, f0.y, acc[q * 2 + 1]);
            }
        }
    }

    float rden = s_rden[g][h];
    float4 b0 = *reinterpret_cast<const float4*>(b1 + lane * 8);
    float4 b1q = *reinterpret_cast<const float4*>(b1 + lane * 8 + 4);
    float ob[8] = {b0.x, b0.y, b0.z, b0.w, b1q.x, b1q.y, b1q.z, b1q.w};
    float o[8];
#pragma unroll
    for (int k = 0; k < 8; k++) {
        float t = acc[k] * rden + ob[k];
        o[k] = t > 0.f ? t : (__expf(t) - 1.f);
    }
    float* hp = g_h1 + (size_t)d * F1 + lane * 8;
    *reinterpret_cast<float4*>(hp) = make_float4(o[0], o[1], o[2], o[3]);
    *reinterpret_cast<float4*>(hp + 4) = make_float4(o[4], o[5], o[6], o[7]);
}

// ---------------- GEMM2: z2[NN,40] = h1[NN,256] @ W2[256,40], fused el2/er2 ----------------
__global__ __launch_bounds__(256) void gemm2_kernel(const float* __restrict__ W,
                                                    const float* __restrict__ al2,
                                                    const float* __restrict__ ar2) {
    __shared__ float Ws[F1][NOUT];
    int tid = threadIdx.x;
    for (int i = tid; i < F1 * NOUT; i += 256) Ws[i / NOUT][i % NOUT] = W[i];
    __syncthreads();

    int r0 = blockIdx.x * 256 + (tid >> 2) * 4;
    int c0 = (tid & 3) * 10;
    float acc[4][10];
#pragma unroll
    for (int i = 0; i < 4; i++)
#pragma unroll
        for (int j = 0; j < 10; j++) acc[i][j] = 0.f;

    bool valid[4];
    const float* ap[4];
#pragma unroll
    for (int i = 0; i < 4; i++) {
        valid[i] = (r0 + i) < NN;
        ap[i] = g_h1 + (size_t)(valid[i] ? (r0 + i) : 0) * F1;
    }
    for (int k0 = 0; k0 < F1; k0 += 4) {
        float4 av[4];
#pragma unroll
        for (int i = 0; i < 4; i++)
            av[i] = valid[i] ? *reinterpret_cast<const float4*>(ap[i] + k0)
                             : make_float4(0.f, 0.f, 0.f, 0.f);
#pragma unroll
        for (int kk = 0; kk < 4; kk++) {
            float a[4];
#pragma unroll
            for (int i = 0; i < 4; i++) a[i] = reinterpret_cast<const float*>(&av[i])[kk];
#pragma unroll
            for (int j = 0; j < 10; j++) {
                float wv = Ws[k0 + kk][c0 + j];
#pragma unroll
                for (int i = 0; i < 4; i++) acc[i][j] += a[i] * wv;
            }
        }
    }

    float alv[10], arv[10];
#pragma unroll
    for (int j = 0; j < 10; j++) { alv[j] = al2[c0 + j]; arv[j] = ar2[c0 + j]; }
#pragma unroll
    for (int i = 0; i < 4; i++) {
        float pl = 0.f, pr = 0.f;
#pragma unroll
        for (int j = 0; j < 10; j++) { pl += acc[i][j] * alv[j]; pr += acc[i][j] * arv[j]; }
        pl += __shfl_xor_sync(0xffffffffu, pl, 1);
        pl += __shfl_xor_sync(0xffffffffu, pl, 2);
        pr += __shfl_xor_sync(0xffffffffu, pr, 1);
        pr += __shfl_xor_sync(0xffffffffu, pr, 2);
        int r = r0 + i;
        if (r < NN) {
            float* cp = g_z2 + (size_t)r * NOUT + c0;
#pragma unroll
            for (int j = 0; j < 10; j++) cp[j] = acc[i][j];
            if ((tid & 3) == 0) { g_el2[r] = pl; g_er2[r] = pr; }
        }
    }
}

// ---------------- fused softmax+aggregation layer 2: warp per dst, 8 dsts/block ----------------
__global__ __launch_bounds__(256) void agg2_kernel(const float* __restrict__ b2,
                                                   float* __restrict__ out) {
    __shared__ float ev2[NDST][CAP2];
    __shared__ int   soff2[NDST][CAP2];   // src*NOUT element offsets
    __shared__ float s_rden[NDST];
    __shared__ int   s_s[NDST], s_deg[NDST];

    int tid = threadIdx.x, w = tid >> 5, lane = tid & 31;
    int d0 = blockIdx.x * NDST;

    if (tid < NDST) {
        int d = d0 + tid;
        int s = g_rowptr[d];
        s_s[tid] = s; s_deg[tid] = g_rowptr[d + 1] - s;
    }
    __syncthreads();

    // phase 1: single-pass softmax
    {
        int g = w, d = d0 + g;
        int s = s_s[g], deg = s_deg[g];
        float erh = g_er2[d];
        float sm = 0.f;
        for (int i = lane; i < deg; i += 32) {
            int src = g_srcs[s + i];
            float x = __expf(lrelu(g_el2[src] + erh));
            if (i < CAP2) { ev2[g][i] = x; soff2[g][i] = src * NOUT; }
            sm += x;
        }
#pragma unroll
        for (int o = 16; o > 0; o >>= 1) sm += __shfl_xor_sync(0xffffffffu, sm, o);
        if (lane == 0) s_rden[g] = sm > 0.f ? 1.f / sm : 0.f;
    }
    __syncthreads();

    // phase 2: aggregate; lane owns col=lane, lanes 0..7 also own col=32+lane
    int g = w, d = d0 + g;
    int s = s_s[g], deg = s_deg[g];
    int dc = deg < CAP2 ? deg : CAP2;
    float acc0 = 0.f, acc1 = 0.f;
    const float* ev = ev2[g];
    const int* sof = soff2[g];
    int i = 0;
    int dn = dc & ~3;
    for (; i < dn; i += 4) {
        int o0 = sof[i], o1 = sof[i + 1], o2 = sof[i + 2], o3 = sof[i + 3];
        float w0 = ev[i], w1 = ev[i + 1], w2 = ev[i + 2], w3 = ev[i + 3];
        acc0 = fmaf(w0, g_z2[o0 + lane], acc0);
        acc0 = fmaf(w1, g_z2[o1 + lane], acc0);
        acc0 = fmaf(w2, g_z2[o2 + lane], acc0);
        acc0 = fmaf(w3, g_z2[o3 + lane], acc0);
        if (lane < 8) {
            acc1 = fmaf(w0, g_z2[o0 + 32 + lane], acc1);
            acc1 = fmaf(w1, g_z2[o1 + 32 + lane], acc1);
            acc1 = fmaf(w2, g_z2[o2 + 32 + lane], acc1);
            acc1 = fmaf(w3, g_z2[o3 + 32 + lane], acc1);
        }
    }
    for (; i < dc; i++) {
        int o0 = sof[i];
        float w0 = ev[i];
        acc0 = fmaf(w0, g_z2[o0 + lane], acc0);
        if (lane < 8) acc1 = fmaf(w0, g_z2[o0 + 32 + lane], acc1);
    }
    if (deg > CAP2) {
        float erh = g_er2[d];
        for (i = CAP2; i < deg; i++) {
            int src = g_srcs[s + i];
            float wgt = __expf(lrelu(g_el2[src] + erh));
            acc0 = fmaf(wgt, g_z2[src * NOUT + lane], acc0);
            if (lane < 8) acc1 = fmaf(wgt, g_z2[src * NOUT + 32 + lane], acc1);
        }
    }
    float rden = s_rden[g];
    out[d * NOUT + lane] = acc0 * rden + b2[lane];
    if (lane < 8) out[d * NOUT + 32 + lane] = acc1 * rden + b2[32 + lane];
}

// ---------------- launch ----------------
extern "C" void kernel_launch(void* const* d_in, const int* in_sizes, int n_in,
                              void* d_out, int out_size) {
    const float* feat = (const float*)d_in[0];
    const int* src = (const int*)d_in[1];
    const int* dst = (const int*)d_in[2];
    const float* W1 = (const float*)d_in[3];
    const float* al1 = (const float*)d_in[4];
    const float* ar1 = (const float*)d_in[5];
    const float* b1 = (const float*)d_in[6];
    const float* W2 = (const float*)d_in[7];
    const float* al2 = (const float*)d_in[8];
    const float* ar2 = (const float*)d_in[9];
    const float* b2 = (const float*)d_in[10];
    float* out = (float*)d_out;

    cudaFuncSetAttribute(gemm1_kernel, cudaFuncAttributeMaxDynamicSharedMemorySize,
                         G1_SMEM_BYTES);

    // (0) GEMM1 (+ fused dst-degree histogram)
    gemm1_kernel<<<G1_TILES + CNT_BLOCKS, 256, G1_SMEM_BYTES>>>(feat, W1, al1, ar1, dst);
    // (1) prefix sum, (2) CSR scatter
    scan_kernel<<<1, 1024>>>();
    scatter_kernel<<<(NE + 255) / 256, 256>>>(src, dst);
    // (3) layer-1 softmax+aggregate  <- profiled launch index
    agg1_kernel<<<NN / NDST, 256>>>(b1);
    // (4) layer-2 GEMM, (5) layer-2 softmax+aggregate
    gemm2_kernel<<<(NN + 255) / 256, 256>>>(W2, al2, ar2);
    agg2_kernel<<<NN / NDST, 256>>>(b2, out);
}

// round 10
// speedup vs baseline: 1.6366x; 1.0277x over previous
#include <cuda_runtime.h>
#include <cuda_fp16.h>
#include <cstdint>

#define NN   50000
#define NE   800000
#define FIN  128
#define NH1  8
#define HID  32
#define F1   256   // NH1*HID
#define NOUT 40
#define NDST 8     // dsts per agg block (warp-per-dst)
#define CAP1 64    // per-dst smem edge cap (max degree ~50 for Poisson(16); fallback exact)
#define EVS  68    // ev stride
#define CAP2 64

// GEMM1 tiling: block 128x128, warp 32x64, BK=32, double-buffered cp.async
#define G1_BM 128
#define G1_BN 128
#define G1_BK 32
#define G1_MTILES (((NN) + G1_BM - 1) / G1_BM)      // 391
#define G1_TILES (G1_MTILES * 2)                    // 782
#define AS_STRIDE 36
#define BS_STRIDE 132
#define AS_ELEMS (G1_BM * AS_STRIDE)
#define BS_ELEMS (G1_BK * BS_STRIDE)
#define G1_SMEM_BYTES ((2 * AS_ELEMS + 2 * BS_ELEMS) * 4)   // 70656

// ---------------- scratch ----------------
__device__ __half g_z1h[(size_t)NN * F1];   // feat @ W1, fp16 (agg1 gather only)
__device__ float  g_h1[(size_t)NN * F1];
__device__ __half g_z2h[(size_t)NN * NOUT]; // h1 @ W2, fp16 (agg2 gather only)
__device__ float g_el1[NN * NH1];
__device__ float g_er1[NN * NH1];
__device__ float g_el2[NN];
__device__ float g_er2[NN];
__device__ int   g_deg[NN];
__device__ int   g_cursor[NN];
__device__ int   g_rowptr[NN + 1];
__device__ int   g_srcs[NE];

// ---------------- helpers ----------------
__device__ __forceinline__ uint32_t f2tf32(float x) {
    uint32_t r;
    asm("cvt.rna.tf32.f32 %0, %1;" : "=r"(r) : "f"(x));
    return r;
}
__device__ __forceinline__ void tf32_split(float x, uint32_t& hi, uint32_t& lo) {
    hi = f2tf32(x);
    lo = f2tf32(x - __uint_as_float(hi));
}
__device__ __forceinline__ void mma_tf32(float* d, const uint32_t* a, uint32_t b0, uint32_t b1) {
    asm volatile(
        "mma.sync.aligned.m16n8k8.row.col.f32.tf32.tf32.f32 "
        "{%0,%1,%2,%3},{%4,%5,%6,%7},{%8,%9},{%0,%1,%2,%3};"
        : "+f"(d[0]), "+f"(d[1]), "+f"(d[2]), "+f"(d[3])
        : "r"(a[0]), "r"(a[1]), "r"(a[2]), "r"(a[3]), "r"(b0), "r"(b1));
}
__device__ __forceinline__ void cpa16(uint32_t dst, const void* src, bool ok) {
    asm volatile("cp.async.cg.shared.global [%0], [%1], 16, %2;"
                 :: "r"(dst), "l"(src), "r"(ok ? 16 : 0));
}
__device__ __forceinline__ void cpa_commit() { asm volatile("cp.async.commit_group;"); }
template <int N>
__device__ __forceinline__ void cpa_wait() { asm volatile("cp.async.wait_group %0;" :: "n"(N)); }
__device__ __forceinline__ float lrelu(float v) { return v > 0.f ? v : 0.2f * v; }

// ---------------- CSR chain (forked stream) ----------------
__global__ void count_kernel(const int* __restrict__ dst) {
    int e = blockIdx.x * blockDim.x + threadIdx.x;
    if (e < NE) atomicAdd(&g_deg[dst[e]], 1);
}

__global__ void scan_kernel() {
    __shared__ int sums[1024];
    int tid = threadIdx.x;
    const int chunk = (NN + 1023) / 1024;
    int start = tid * chunk;
    int end = start + chunk; if (end > NN) end = NN;
    int local = 0;
    for (int i = start; i < end; i++) local += g_deg[i];
    sums[tid] = local;
    __syncthreads();
    for (int off = 1; off < 1024; off <<= 1) {
        int v = 0;
        if (tid >= off) v = sums[tid - off];
        __syncthreads();
        if (tid >= off) sums[tid] += v;
        __syncthreads();
    }
    int run = (tid == 0) ? 0 : sums[tid - 1];
    for (int i = start; i < end; i++) {
        g_rowptr[i] = run;
        run += g_deg[i];
        g_cursor[i] = 0;
    }
    if (tid == 1023) g_rowptr[NN] = run;
}

__global__ void scatter_kernel(const int* __restrict__ src, const int* __restrict__ dst) {
    int e = blockIdx.x * blockDim.x + threadIdx.x;
    if (e >= NE) return;
    int d = dst[e];
    int p = atomicAdd(&g_cursor[d], 1);
    g_srcs[g_rowptr[d] + p] = src[e];
}

// ---------------- GEMM1 (tf32 2-term: (a_hi+a_lo)*b_hi), fused el1/er1 ----------------
__global__ __launch_bounds__(256, 2) void gemm1_kernel(const float* __restrict__ A,
                                                       const float* __restrict__ B,
                                                       const float* __restrict__ al,
                                                       const float* __restrict__ ar) {
    int tid = threadIdx.x;
    extern __shared__ float smx[];
    float* Asm[2] = { smx, smx + AS_ELEMS };
    float* Bsm[2] = { smx + 2 * AS_ELEMS, smx + 2 * AS_ELEMS + BS_ELEMS };

    int wid = tid >> 5, lane = tid & 31;
    int wm = wid >> 1, wn = wid & 1;
    int r = lane >> 2, c = lane & 3;
    int brow = (blockIdx.x >> 1) * G1_BM;
    int bcol = (blockIdx.x & 1) * G1_BN;

    int la_row = tid >> 1;
    int la_kq = (tid & 1) * 16;
    int la_gr = brow + la_row;
    bool la_ok = la_gr < NN;
    const float* la_src = A + (size_t)(la_ok ? la_gr : 0) * FIN + la_kq;
    int lb_row = tid >> 3;
    int lb_col = (tid & 7) * 16;

    auto issue = [&](int kc, int buf) {
        uint32_t ad = (uint32_t)__cvta_generic_to_shared(Asm[buf] + la_row * AS_STRIDE + la_kq);
        const float* as = la_src + kc * G1_BK;
#pragma unroll
        for (int i = 0; i < 4; i++) cpa16(ad + i * 16, as + i * 4, la_ok);
        uint32_t bd = (uint32_t)__cvta_generic_to_shared(Bsm[buf] + lb_row * BS_STRIDE + lb_col);
        const float* bs = B + (size_t)(kc * G1_BK + lb_row) * F1 + bcol + lb_col;
#pragma unroll
        for (int i = 0; i < 4; i++) cpa16(bd + i * 16, bs + i * 4, true);
    };

    float acc[2][8][4];
#pragma unroll
    for (int mt = 0; mt < 2; mt++)
#pragma unroll
        for (int nt = 0; nt < 8; nt++)
#pragma unroll
            for (int j = 0; j < 4; j++) acc[mt][nt][j] = 0.f;

    issue(0, 0); cpa_commit();
    issue(1, 1); cpa_commit();
    cpa_wait<1>();
    __syncthreads();

#pragma unroll
    for (int kc = 0; kc < 4; kc++) {
        int buf = kc & 1;
        const float* as = Asm[buf];
        const float* bs = Bsm[buf];
#pragma unroll
        for (int ks = 0; ks < 4; ks++) {
            int k0 = ks * 8;
            uint32_t bh0[8], bh1[8];
            int bcl = wn * 64 + r;
#pragma unroll
            for (int nt = 0; nt < 8; nt++) {
                bh0[nt] = f2tf32(bs[(k0 + c) * BS_STRIDE + bcl + nt * 8]);
                bh1[nt] = f2tf32(bs[(k0 + 4 + c) * BS_STRIDE + bcl + nt * 8]);
            }
#pragma unroll
            for (int mt = 0; mt < 2; mt++) {
                int mr = wm * 32 + mt * 16 + r;
                float a0 = as[mr * AS_STRIDE + k0 + c];
                float a1 = as[(mr + 8) * AS_STRIDE + k0 + c];
                float a2 = as[mr * AS_STRIDE + k0 + 4 + c];
                float a3 = as[(mr + 8) * AS_STRIDE + k0 + 4 + c];
                uint32_t ah[4], alo[4];
                tf32_split(a0, ah[0], alo[0]);
                tf32_split(a1, ah[1], alo[1]);
                tf32_split(a2, ah[2], alo[2]);
                tf32_split(a3, ah[3], alo[3]);
#pragma unroll
                for (int nt = 0; nt < 8; nt++) {
                    mma_tf32(acc[mt][nt], ah, bh0[nt], bh1[nt]);
                    mma_tf32(acc[mt][nt], alo, bh0[nt], bh1[nt]);
                }
            }
        }
        __syncthreads();
        if (kc == 0 || kc == 1) issue(kc + 2, buf);
        cpa_commit();
        if (kc < 3) {
            cpa_wait<1>();
            __syncthreads();
        }
    }

    float alv[16], arv[16];
#pragma unroll
    for (int nt = 0; nt < 8; nt++)
#pragma unroll
        for (int j = 0; j < 2; j++) {
            int head = (bcol >> 5) + wn * 2 + (nt >> 2);
            int cih = (nt & 3) * 8 + c * 2 + j;
            alv[nt * 2 + j] = al[head * HID + cih];
            arv[nt * 2 + j] = ar[head * HID + cih];
        }

#pragma unroll
    for (int mt = 0; mt < 2; mt++) {
        int r0 = brow + wm * 32 + mt * 16 + r;
        int r1 = r0 + 8;
        float el[2][2] = {{0.f, 0.f}, {0.f, 0.f}};
        float er_[2][2] = {{0.f, 0.f}, {0.f, 0.f}};
#pragma unroll
        for (int nt = 0; nt < 8; nt++) {
            int hh = nt >> 2;
#pragma unroll
            for (int j = 0; j < 2; j++) {
                float av = alv[nt * 2 + j], rv = arv[nt * 2 + j];
                el[hh][0] += acc[mt][nt][j] * av;
                er_[hh][0] += acc[mt][nt][j] * rv;
                el[hh][1] += acc[mt][nt][2 + j] * av;
                er_[hh][1] += acc[mt][nt][2 + j] * rv;
            }
        }
#pragma unroll
        for (int hh = 0; hh < 2; hh++)
#pragma unroll
            for (int hf = 0; hf < 2; hf++) {
                el[hh][hf] += __shfl_xor_sync(0xffffffffu, el[hh][hf], 1);
                el[hh][hf] += __shfl_xor_sync(0xffffffffu, el[hh][hf], 2);
                er_[hh][hf] += __shfl_xor_sync(0xffffffffu, er_[hh][hf], 1);
                er_[hh][hf] += __shfl_xor_sync(0xffffffffu, er_[hh][hf], 2);
            }
        if (r0 < NN) {
            __half* p0 = g_z1h + (size_t)r0 * F1 + bcol + wn * 64 + c * 2;
#pragma unroll
            for (int nt = 0; nt < 8; nt++)
                *reinterpret_cast<__half2*>(p0 + nt * 8) = __floats2half2_rn(acc[mt][nt][0], acc[mt][nt][1]);
        }
        if (r1 < NN) {
            __half* p1 = g_z1h + (size_t)r1 * F1 + bcol + wn * 64 + c * 2;
#pragma unroll
            for (int nt = 0; nt < 8; nt++)
                *reinterpret_cast<__half2*>(p1 + nt * 8) = __floats2half2_rn(acc[mt][nt][2], acc[mt][nt][3]);
        }
        if (c == 0) {
#pragma unroll
            for (int hh = 0; hh < 2; hh++) {
                int head = (bcol >> 5) + wn * 2 + hh;
                if (r0 < NN) { g_el1[r0 * NH1 + head] = el[hh][0]; g_er1[r0 * NH1 + head] = er_[hh][0]; }
                if (r1 < NN) { g_el1[r1 * NH1 + head] = el[hh][1]; g_er1[r1 * NH1 + head] = er_[hh][1]; }
            }
        }
    }
}

// ---------------- fused softmax+aggregation layer 1: warp per dst, 8 dsts/block ----------------
__global__ __launch_bounds__(256) void agg1_kernel(const float* __restrict__ b1) {
    __shared__ int   soff[NDST][CAP1];
    __shared__ float ev[NDST][NH1][EVS];
    __shared__ float s_rden[NDST][NH1];
    __shared__ int   s_s[NDST], s_deg[NDST];

    int tid = threadIdx.x, w = tid >> 5, lane = tid & 31;
    int d0 = blockIdx.x * NDST;

    if (tid < NDST) {
        int d = d0 + tid;
        int s = g_rowptr[d];
        s_s[tid] = s; s_deg[tid] = g_rowptr[d + 1] - s;
        g_deg[d] = 0;   // restore invariant for next call's count
    }
    __syncthreads();

    {
        int g = w, d = d0 + g;
        int s = s_s[g], deg = s_deg[g];
        const float4* erv = reinterpret_cast<const float4*>(g_er1 + d * NH1);
        float4 er0 = erv[0], er1q = erv[1];
        float er[8] = {er0.x, er0.y, er0.z, er0.w, er1q.x, er1q.y, er1q.z, er1q.w};
        float sm[8];
#pragma unroll
        for (int k = 0; k < 8; k++) sm[k] = 0.f;
        for (int i = lane; i < deg; i += 32) {
            int src = g_srcs[s + i];
            const float4* elv = reinterpret_cast<const float4*>(g_el1 + src * NH1);
            float4 e0 = elv[0], e1 = elv[1];
            float x[8] = {__expf(lrelu(e0.x + er[0])), __expf(lrelu(e0.y + er[1])),
                          __expf(lrelu(e0.z + er[2])), __expf(lrelu(e0.w + er[3])),
                          __expf(lrelu(e1.x + er[4])), __expf(lrelu(e1.y + er[5])),
                          __expf(lrelu(e1.z + er[6])), __expf(lrelu(e1.w + er[7]))};
            if (i < CAP1) {
#pragma unroll
                for (int k = 0; k < 8; k++) ev[g][k][i] = x[k];
                soff[g][i] = src << 9;
            }
#pragma unroll
            for (int k = 0; k < 8; k++) sm[k] += x[k];
        }
#pragma unroll
        for (int k = 0; k < 8; k++)
#pragma unroll
            for (int o = 16; o > 0; o >>= 1) sm[k] += __shfl_xor_sync(0xffffffffu, sm[k], o);
        if (lane == 0) {
#pragma unroll
            for (int k = 0; k < 8; k++) s_rden[g][k] = sm[k] > 0.f ? 1.f / sm[k] : 0.f;
        }
    }
    __syncthreads();

    int g = w, d = d0 + g;
    int s = s_s[g], deg = s_deg[g];
    int dc = deg < CAP1 ? deg : CAP1;
    int h = lane >> 2;
    const char* zb = (const char*)g_z1h + lane * 16;
    const float* evh = ev[g][h];
    const int* sof = soff[g];
    float acc[8];
#pragma unroll
    for (int k = 0; k < 8; k++) acc[k] = 0.f;

    int i = 0;
    int dn = dc & ~3;
    for (; i < dn; i += 4) {
        int o0 = sof[i], o1 = sof[i + 1], o2 = sof[i + 2], o3 = sof[i + 3];
        float w0 = evh[i], w1 = evh[i + 1], w2 = evh[i + 2], w3 = evh[i + 3];
        uint4 v0 = *reinterpret_cast<const uint4*>(zb + o0);
        uint4 v1 = *reinterpret_cast<const uint4*>(zb + o1);
        uint4 v2 = *reinterpret_cast<const uint4*>(zb + o2);
        uint4 v3 = *reinterpret_cast<const uint4*>(zb + o3);
#pragma unroll
        for (int q = 0; q < 4; q++) {
            uint32_t u0 = (&v0.x)[q], u1 = (&v1.x)[q], u2 = (&v2.x)[q], u3 = (&v3.x)[q];
            float2 f0 = __half22float2(*reinterpret_cast<__half2*>(&u0));
            float2 f1 = __half22float2(*reinterpret_cast<__half2*>(&u1));
            float2 f2 = __half22float2(*reinterpret_cast<__half2*>(&u2));
            float2 f3 = __half22float2(*reinterpret_cast<__half2*>(&u3));
            acc[q * 2]     = fmaf(w0, f0.x, acc[q * 2]);
            acc[q * 2 + 1] = fmaf(w0, f0.y, acc[q * 2 + 1]);
            acc[q * 2]     = fmaf(w1, f1.x, acc[q * 2]);
            acc[q * 2 + 1] = fmaf(w1, f1.y, acc[q * 2 + 1]);
            acc[q * 2]     = fmaf(w2, f2.x, acc[q * 2]);
            acc[q * 2 + 1] = fmaf(w2, f2.y, acc[q * 2 + 1]);
            acc[q * 2]     = fmaf(w3, f3.x, acc[q * 2]);
            acc[q * 2 + 1] = fmaf(w3, f3.y, acc[q * 2 + 1]);
        }
    }
    for (; i < dc; i++) {
        int o0 = sof[i];
        float w0 = evh[i];
        uint4 v0 = *reinterpret_cast<const uint4*>(zb + o0);
#pragma unroll
        for (int q = 0; q < 4; q++) {
            uint32_t u0 = (&v0.x)[q];
            float2 f0 = __half22float2(*reinterpret_cast<__half2*>(&u0));
            acc[q * 2]     = fmaf(w0, f0.x, acc[q * 2]);
            acc[q * 2 + 1] = fmaf(w0, f0.y, acc[q * 2 + 1]);
        }
    }
    if (deg > CAP1) {
        float erh = g_er1[d * NH1 + h];
        for (i = CAP1; i < deg; i++) {
            int src = g_srcs[s + i];
            float wgt = __expf(lrelu(g_el1[src * NH1 + h] + erh));
            uint4 v0 = *reinterpret_cast<const uint4*>(zb + (src << 9));
#pragma unroll
            for (int q = 0; q < 4; q++) {
                uint32_t u0 = (&v0.x)[q];
                float2 f0 = __half22float2(*reinterpret_cast<__half2*>(&u0));
                acc[q * 2]     = fmaf(wgt, f0.x, acc[q * 2]);
                acc[q * 2 + 1] = fmaf(wgt, f0.y, acc[q * 2 + 1]);
            }
        }
    }

    float rden = s_rden[g][h];
    float4 b0 = *reinterpret_cast<const float4*>(b1 + lane * 8);
    float4 b1q = *reinterpret_cast<const float4*>(b1 + lane * 8 + 4);
    float ob[8] = {b0.x, b0.y, b0.z, b0.w, b1q.x, b1q.y, b1q.z, b1q.w};
    float o[8];
#pragma unroll
    for (int k = 0; k < 8; k++) {
        float t = acc[k] * rden + ob[k];
        o[k] = t > 0.f ? t : (__expf(t) - 1.f);
    }
    float* hp = g_h1 + (size_t)d * F1 + lane * 8;
    *reinterpret_cast<float4*>(hp) = make_float4(o[0], o[1], o[2], o[3]);
    *reinterpret_cast<float4*>(hp + 4) = make_float4(o[4], o[5], o[6], o[7]);
}

// ---------------- GEMM2: z2h[NN,40] = h1 @ W2 (fp16 out), fused el2/er2 ----------------
__global__ __launch_bounds__(256) void gemm2_kernel(const float* __restrict__ W,
                                                    const float* __restrict__ al2,
                                                    const float* __restrict__ ar2) {
    __shared__ float Ws[F1][NOUT];
    int tid = threadIdx.x;
    for (int i = tid; i < F1 * NOUT; i += 256) Ws[i / NOUT][i % NOUT] = W[i];
    __syncthreads();

    int r0 = blockIdx.x * 256 + (tid >> 2) * 4;
    int c0 = (tid & 3) * 10;
    float acc[4][10];
#pragma unroll
    for (int i = 0; i < 4; i++)
#pragma unroll
        for (int j = 0; j < 10; j++) acc[i][j] = 0.f;

    bool valid[4];
    const float* ap[4];
#pragma unroll
    for (int i = 0; i < 4; i++) {
        valid[i] = (r0 + i) < NN;
        ap[i] = g_h1 + (size_t)(valid[i] ? (r0 + i) : 0) * F1;
    }
    for (int k0 = 0; k0 < F1; k0 += 4) {
        float4 av[4];
#pragma unroll
        for (int i = 0; i < 4; i++)
            av[i] = valid[i] ? *reinterpret_cast<const float4*>(ap[i] + k0)
                             : make_float4(0.f, 0.f, 0.f, 0.f);
#pragma unroll
        for (int kk = 0; kk < 4; kk++) {
            float a[4];
#pragma unroll
            for (int i = 0; i < 4; i++) a[i] = reinterpret_cast<const float*>(&av[i])[kk];
#pragma unroll
            for (int j = 0; j < 10; j++) {
                float wv = Ws[k0 + kk][c0 + j];
#pragma unroll
                for (int i = 0; i < 4; i++) acc[i][j] += a[i] * wv;
            }
        }
    }

    float alv[10], arv[10];
#pragma unroll
    for (int j = 0; j < 10; j++) { alv[j] = al2[c0 + j]; arv[j] = ar2[c0 + j]; }
#pragma unroll
    for (int i = 0; i < 4; i++) {
        float pl = 0.f, pr = 0.f;
#pragma unroll
        for (int j = 0; j < 10; j++) { pl += acc[i][j] * alv[j]; pr += acc[i][j] * arv[j]; }
        pl += __shfl_xor_sync(0xffffffffu, pl, 1);
        pl += __shfl_xor_sync(0xffffffffu, pl, 2);
        pr += __shfl_xor_sync(0xffffffffu, pr, 1);
        pr += __shfl_xor_sync(0xffffffffu, pr, 2);
        int r = r0 + i;
        if (r < NN) {
            __half2* cp = reinterpret_cast<__half2*>(g_z2h + (size_t)r * NOUT + c0);
#pragma unroll
            for (int j = 0; j < 5; j++)
                cp[j] = __floats2half2_rn(acc[i][2 * j], acc[i][2 * j + 1]);
            if ((tid & 3) == 0) { g_el2[r] = pl; g_er2[r] = pr; }
        }
    }
}

// ---------------- fused softmax+aggregation layer 2: warp per dst (fp16 z2 gather) ----------------
__global__ __launch_bounds__(256) void agg2_kernel(const float* __restrict__ b2,
                                                   float* __restrict__ out) {
    __shared__ float ev2[NDST][CAP2];
    __shared__ int   soff2[NDST][CAP2];   // src*80 byte offsets
    __shared__ float s_rden[NDST];
    __shared__ int   s_s[NDST], s_deg[NDST];

    int tid = threadIdx.x, w = tid >> 5, lane = tid & 31;
    int d0 = blockIdx.x * NDST;

    if (tid < NDST) {
        int d = d0 + tid;
        int s = g_rowptr[d];
        s_s[tid] = s; s_deg[tid] = g_rowptr[d + 1] - s;
    }
    __syncthreads();

    {
        int g = w, d = d0 + g;
        int s = s_s[g], deg = s_deg[g];
        float erh = g_er2[d];
        float sm = 0.f;
        for (int i = lane; i < deg; i += 32) {
            int src = g_srcs[s + i];
            float x = __expf(lrelu(g_el2[src] + erh));
            if (i < CAP2) { ev2[g][i] = x; soff2[g][i] = src * (NOUT * 2); }
            sm += x;
        }
#pragma unroll
        for (int o = 16; o > 0; o >>= 1) sm += __shfl_xor_sync(0xffffffffu, sm, o);
        if (lane == 0) s_rden[g] = sm > 0.f ? 1.f / sm : 0.f;
    }
    __syncthreads();

    // phase 2: lanes 0..19 own cols {2*lane, 2*lane+1} via half2 loads
    int g = w, d = d0 + g;
    int s = s_s[g], deg = s_deg[g];
    int dc = deg < CAP2 ? deg : CAP2;
    const float* ev = ev2[g];
    const int* sof = soff2[g];
    float accx = 0.f, accy = 0.f;
    const char* zb = (const char*)g_z2h + lane * 4;
    bool active = lane < 20;
    int i = 0;
    int dn = dc & ~3;
    for (; i < dn; i += 4) {
        int o0 = sof[i], o1 = sof[i + 1], o2 = sof[i + 2], o3 = sof[i + 3];
        float w0 = ev[i], w1 = ev[i + 1], w2 = ev[i + 2], w3 = ev[i + 3];
        if (active) {
            uint32_t u0 = *reinterpret_cast<const uint32_t*>(zb + o0);
            uint32_t u1 = *reinterpret_cast<const uint32_t*>(zb + o1);
            uint32_t u2 = *reinterpret_cast<const uint32_t*>(zb + o2);
            uint32_t u3 = *reinterpret_cast<const uint32_t*>(zb + o3);
            float2 f0 = __half22float2(*reinterpret_cast<__half2*>(&u0));
            float2 f1 = __half22float2(*reinterpret_cast<__half2*>(&u1));
            float2 f2 = __half22float2(*reinterpret_cast<__half2*>(&u2));
            float2 f3 = __half22float2(*reinterpret_cast<__half2*>(&u3));
            accx = fmaf(w0, f0.x, accx); accy = fmaf(w0, f0.y, accy);
            accx = fmaf(w1, f1.x, accx); accy = fmaf(w1, f1.y, accy);
            accx = fmaf(w2, f2.x, accx); accy = fmaf(w2, f2.y, accy);
            accx = fmaf(w3, f3.x, accx); accy = fmaf(w3, f3.y, accy);
        }
    }
    for (; i < dc; i++) {
        int o0 = sof[i];
        float w0 = ev[i];
        if (active) {
            uint32_t u0 = *reinterpret_cast<const uint32_t*>(zb + o0);
            float2 f0 = __half22float2(*reinterpret_cast<__half2*>(&u0));
            accx = fmaf(w0, f0.x, accx); accy = fmaf(w0, f0.y, accy);
        }
    }
    if (deg > CAP2) {
        float erh = g_er2[d];
        for (i = CAP2; i < deg; i++) {
            int src = g_srcs[s + i];
            float wgt = __expf(lrelu(g_el2[src] + erh));
            if (active) {
                uint32_t u0 = *reinterpret_cast<const uint32_t*>(zb + src * (NOUT * 2));
                float2 f0 = __half22float2(*reinterpret_cast<__half2*>(&u0));
                accx = fmaf(wgt, f0.x, accx); accy = fmaf(wgt, f0.y, accy);
            }
        }
    }
    if (active) {
        float rden = s_rden[g];
        float2 bb = *reinterpret_cast<const float2*>(b2 + 2 * lane);
        float2 ov = make_float2(accx * rden + bb.x, accy * rden + bb.y);
        *reinterpret_cast<float2*>(out + (size_t)d * NOUT + 2 * lane) = ov;
    }
}

// ---------------- launch ----------------
extern "C" void kernel_launch(void* const* d_in, const int* in_sizes, int n_in,
                              void* d_out, int out_size) {
    const float* feat = (const float*)d_in[0];
    const int* src = (const int*)d_in[1];
    const int* dst = (const int*)d_in[2];
    const float* W1 = (const float*)d_in[3];
    const float* al1 = (const float*)d_in[4];
    const float* ar1 = (const float*)d_in[5];
    const float* b1 = (const float*)d_in[6];
    const float* W2 = (const float*)d_in[7];
    const float* al2 = (const float*)d_in[8];
    const float* ar2 = (const float*)d_in[9];
    const float* b2 = (const float*)d_in[10];
    float* out = (float*)d_out;

    // Host-side resources created ONCE and never destroyed: destroying a stream
    // that participated in an ongoing capture invalidates the capture. Work
    // enqueued is identical on every call (deterministic).
    static cudaStream_t s2 = nullptr;
    static cudaEvent_t evFork = nullptr, evJoin = nullptr;
    if (s2 == nullptr) {
        cudaStreamCreateWithFlags(&s2, cudaStreamNonBlocking);
        cudaEventCreateWithFlags(&evFork, cudaEventDisableTiming);
        cudaEventCreateWithFlags(&evJoin, cudaEventDisableTiming);
        cudaFuncSetAttribute(gemm1_kernel, cudaFuncAttributeMaxDynamicSharedMemorySize,
                             G1_SMEM_BYTES);
    }

    // fork: CSR chain on s2, GEMM1 on main stream (independent until agg1)
    cudaEventRecord(evFork, 0);
    cudaStreamWaitEvent(s2, evFork, 0);

    count_kernel<<<(NE + 255) / 256, 256, 0, s2>>>(dst);
    scan_kernel<<<1, 1024, 0, s2>>>();
    scatter_kernel<<<(NE + 255) / 256, 256, 0, s2>>>(src, dst);
    cudaEventRecord(evJoin, s2);

    gemm1_kernel<<<G1_TILES, 256, G1_SMEM_BYTES>>>(feat, W1, al1, ar1);

    cudaStreamWaitEvent(0, evJoin, 0);

    // layer-1 softmax+aggregate, then layer 2
    agg1_kernel<<<NN / NDST, 256>>>(b1);
    gemm2_kernel<<<(NN + 255) / 256, 256>>>(W2, al2, ar2);
    agg2_kernel<<<NN / NDST, 256>>>(b2, out);
}